// round 8
// baseline (speedup 1.0000x reference)
#include <cuda_runtime.h>
#include <cuda_bf16.h>
#include <cstdint>

#define HD 2048
#define NH 16
#define DH 128
#define BB 2
#define SQ 2048
#define MR (BB*SQ)   // 4096 rows

// ---------------------------------------------------------------------------
// Scratch (device globals; no allocations allowed)
// ---------------------------------------------------------------------------
__device__ __nv_bfloat16 g_Qhi[(size_t)MR*HD];
__device__ __nv_bfloat16 g_Qlo[(size_t)MR*HD];
__device__ __nv_bfloat16 g_Khi[(size_t)MR*HD];
__device__ __nv_bfloat16 g_Klo[(size_t)MR*HD];
__device__ __nv_bfloat16 g_Vhi[(size_t)MR*HD];
__device__ __nv_bfloat16 g_Vlo[(size_t)MR*HD];
__device__ __nv_bfloat16 g_Ahi[(size_t)MR*HD];
__device__ __nv_bfloat16 g_Alo[(size_t)MR*HD];
__device__ __nv_bfloat16 g_Xhi[(size_t)MR*HD];
__device__ __nv_bfloat16 g_Xlo[(size_t)MR*HD];
__device__ __nv_bfloat16 g_Wthi[4][(size_t)HD*HD];   // transposed: [n][k]; Q,K,V contiguous
__device__ __nv_bfloat16 g_Wtlo[4][(size_t)HD*HD];

// ---------------------------------------------------------------------------
// PTX helpers (compute_103-safe: mma.sync / ldmatrix / cp.async only)
// ---------------------------------------------------------------------------
__device__ __forceinline__ uint32_t smem_to_u32(const void* p) {
    uint32_t a;
    asm("{ .reg .u64 t; cvta.to.shared.u64 t, %1; cvt.u32.u64 %0, t; }"
        : "=r"(a) : "l"(p));
    return a;
}
__device__ __forceinline__ void cp_async16(uint32_t s, const void* g) {
    asm volatile("cp.async.cg.shared.global [%0], [%1], 16;" :: "r"(s), "l"(g));
}
#define CP_COMMIT() asm volatile("cp.async.commit_group;" ::: "memory")
#define CP_WAIT(n)  asm volatile("cp.async.wait_group %0;" :: "n"(n) : "memory")

__device__ __forceinline__ void ldsm_x4(uint32_t& r0, uint32_t& r1,
                                        uint32_t& r2, uint32_t& r3, uint32_t addr) {
    asm volatile("ldmatrix.sync.aligned.m8n8.x4.shared.b16 {%0,%1,%2,%3}, [%4];"
        : "=r"(r0), "=r"(r1), "=r"(r2), "=r"(r3) : "r"(addr));
}
__device__ __forceinline__ void ldsm_x4_t(uint32_t& r0, uint32_t& r1,
                                          uint32_t& r2, uint32_t& r3, uint32_t addr) {
    asm volatile("ldmatrix.sync.aligned.m8n8.x4.trans.shared.b16 {%0,%1,%2,%3}, [%4];"
        : "=r"(r0), "=r"(r1), "=r"(r2), "=r"(r3) : "r"(addr));
}
__device__ __forceinline__ void mma_bf16(float* c, const uint32_t* a,
                                         uint32_t b0, uint32_t b1) {
    asm volatile(
        "mma.sync.aligned.m16n8k16.row.col.f32.bf16.bf16.f32 "
        "{%0,%1,%2,%3}, {%4,%5,%6,%7}, {%8,%9}, {%0,%1,%2,%3};"
        : "+f"(c[0]), "+f"(c[1]), "+f"(c[2]), "+f"(c[3])
        : "r"(a[0]), "r"(a[1]), "r"(a[2]), "r"(a[3]), "r"(b0), "r"(b1));
}
__device__ __forceinline__ uint32_t pack_bf2(__nv_bfloat16 a, __nv_bfloat16 b) {
    __nv_bfloat162 t(a, b);
    return *(uint32_t*)&t;
}
__device__ __forceinline__ void split_pack(float x, float y, uint32_t& hi, uint32_t& lo) {
    __nv_bfloat16 hx = __float2bfloat16(x);
    __nv_bfloat16 hy = __float2bfloat16(y);
    __nv_bfloat16 lx = __float2bfloat16(x - __bfloat162float(hx));
    __nv_bfloat16 ly = __float2bfloat16(y - __bfloat162float(hy));
    hi = pack_bf2(hx, hy);
    lo = pack_bf2(lx, ly);
}

// ---------------------------------------------------------------------------
// Conversion kernels
// ---------------------------------------------------------------------------
__global__ __launch_bounds__(256) void cvt_split_kernel(
    const float4* __restrict__ in, __nv_bfloat16* __restrict__ hi,
    __nv_bfloat16* __restrict__ lo, int n4)
{
    int i = blockIdx.x * 256 + threadIdx.x;
    if (i >= n4) return;
    float4 v = in[i];
    float f[4] = {v.x, v.y, v.z, v.w};
    #pragma unroll
    for (int p = 0; p < 2; p++) {
        uint32_t h, l;
        split_pack(f[2*p+0], f[2*p+1], h, l);
        ((uint32_t*)hi)[2*i+p] = h;
        ((uint32_t*)lo)[2*i+p] = l;
    }
}

__global__ __launch_bounds__(256) void cvt_wt_kernel(
    const float* __restrict__ W0, const float* __restrict__ W1,
    const float* __restrict__ W2, const float* __restrict__ W3,
    __nv_bfloat16* __restrict__ hib, __nv_bfloat16* __restrict__ lob)
{
    __shared__ float tile[32][33];
    const int z = blockIdx.z;
    const float* W = (z == 0) ? W0 : (z == 1) ? W1 : (z == 2) ? W2 : W3;
    __nv_bfloat16* hi = hib + (size_t)z * HD * HD;
    __nv_bfloat16* lo = lob + (size_t)z * HD * HD;
    const int n0 = blockIdx.x * 32, k0 = blockIdx.y * 32;
    const int tx = threadIdx.x, ty = threadIdx.y;
    #pragma unroll
    for (int i = 0; i < 4; i++)
        tile[ty + 8*i][tx] = W[(size_t)(k0 + ty + 8*i) * HD + n0 + tx];
    __syncthreads();
    #pragma unroll
    for (int i = 0; i < 4; i++) {
        float v = tile[tx][ty + 8*i];
        __nv_bfloat16 h = __float2bfloat16(v);
        __nv_bfloat16 l = __float2bfloat16(v - __bfloat162float(h));
        size_t idx = (size_t)(n0 + ty + 8*i) * HD + k0 + tx;
        hi[idx] = h;
        lo[idx] = l;
    }
}

// ---------------------------------------------------------------------------
// mma.sync GEMM (unchanged from round 7)
// ---------------------------------------------------------------------------
#define KC 32
#define PITCHB 80
#define TILE_BYTES (128 * PITCHB)
#define STAGE_BYTES (4 * TILE_BYTES)
#define GEMM_SMEM (2 * STAGE_BYTES)     // 81920

template<int MODE>
__global__ __launch_bounds__(256, 2) void gemm_mma_kernel(
    const __nv_bfloat16* __restrict__ Ahi, const __nv_bfloat16* __restrict__ Alo,
    const __nv_bfloat16* __restrict__ Bhi, const __nv_bfloat16* __restrict__ Blo,
    const float* __restrict__ b0, const float* __restrict__ b1,
    const float* __restrict__ b2,
    __nv_bfloat16* __restrict__ o0h, __nv_bfloat16* __restrict__ o0l,
    __nv_bfloat16* __restrict__ o1h, __nv_bfloat16* __restrict__ o1l,
    __nv_bfloat16* __restrict__ o2h, __nv_bfloat16* __restrict__ o2l,
    float* __restrict__ Cf)
{
    extern __shared__ __align__(128) char smem[];
    const uint32_t sbase = smem_to_u32(smem);
    const int tid  = threadIdx.x;
    const int wid  = tid >> 5;
    const int lane = tid & 31;
    const int bm = blockIdx.y * 128;
    const int bn = blockIdx.x * 128;
    const int wm = (wid >> 2) * 64;
    const int wn = (wid & 3) * 32;

    float acc[4][4][4];
    #pragma unroll
    for (int mt = 0; mt < 4; mt++)
        #pragma unroll
        for (int nt = 0; nt < 4; nt++)
            #pragma unroll
            for (int i = 0; i < 4; i++) acc[mt][nt][i] = 0.f;

    const int lr = tid >> 2;
    const int lc = tid & 3;

    {
        const uint32_t sb = sbase;
        #pragma unroll
        for (int i = 0; i < 2; i++) {
            int r = lr + i * 64;
            uint32_t off = (uint32_t)r * PITCHB + lc * 16;
            size_t ga = (size_t)(bm + r) * HD + lc * 8;
            size_t gb = (size_t)(bn + r) * HD + lc * 8;
            cp_async16(sb + 0*TILE_BYTES + off, Ahi + ga);
            cp_async16(sb + 1*TILE_BYTES + off, Alo + ga);
            cp_async16(sb + 2*TILE_BYTES + off, Bhi + gb);
            cp_async16(sb + 3*TILE_BYTES + off, Blo + gb);
        }
        CP_COMMIT();
    }

    const int r8 = lane & 7;
    const int g  = lane >> 3;
    const uint32_t a_row_add = (uint32_t)(r8 + ((g & 1) ? 8 : 0)) * PITCHB + ((g & 2) ? 16 : 0);
    const uint32_t b_row_add = (uint32_t)(r8 + ((g >= 2) ? 8 : 0)) * PITCHB + ((g & 1) ? 16 : 0);

    for (int t = 0; t < HD / KC; t++) {
        if (t + 1 < HD / KC) {
            const int k0 = (t + 1) * KC;
            const uint32_t sb = sbase + ((t + 1) & 1) * STAGE_BYTES;
            #pragma unroll
            for (int i = 0; i < 2; i++) {
                int r = lr + i * 64;
                uint32_t off = (uint32_t)r * PITCHB + lc * 16;
                size_t ga = (size_t)(bm + r) * HD + k0 + lc * 8;
                size_t gb = (size_t)(bn + r) * HD + k0 + lc * 8;
                cp_async16(sb + 0*TILE_BYTES + off, Ahi + ga);
                cp_async16(sb + 1*TILE_BYTES + off, Alo + ga);
                cp_async16(sb + 2*TILE_BYTES + off, Bhi + gb);
                cp_async16(sb + 3*TILE_BYTES + off, Blo + gb);
            }
            CP_COMMIT();
            CP_WAIT(1);
        } else {
            CP_WAIT(0);
        }
        __syncthreads();

        const uint32_t sb = sbase + (t & 1) * STAGE_BYTES;
        #pragma unroll
        for (int ks = 0; ks < 2; ks++) {
            uint32_t bh[2][4], bl[2][4];
            #pragma unroll
            for (int p = 0; p < 2; p++) {
                uint32_t addr = sb + (uint32_t)(wn + p * 16) * PITCHB + ks * 32 + b_row_add;
                ldsm_x4(bh[p][0], bh[p][1], bh[p][2], bh[p][3], addr + 2*TILE_BYTES);
                ldsm_x4(bl[p][0], bl[p][1], bl[p][2], bl[p][3], addr + 3*TILE_BYTES);
            }
            #pragma unroll
            for (int mt = 0; mt < 4; mt++) {
                uint32_t ah[4], al[4];
                uint32_t addr = sb + (uint32_t)(wm + mt * 16) * PITCHB + ks * 32 + a_row_add;
                ldsm_x4(ah[0], ah[1], ah[2], ah[3], addr + 0*TILE_BYTES);
                ldsm_x4(al[0], al[1], al[2], al[3], addr + 1*TILE_BYTES);
                #pragma unroll
                for (int nt = 0; nt < 4; nt++) {
                    uint32_t bh0 = bh[nt >> 1][(nt & 1) * 2 + 0];
                    uint32_t bh1 = bh[nt >> 1][(nt & 1) * 2 + 1];
                    uint32_t bl0 = bl[nt >> 1][(nt & 1) * 2 + 0];
                    uint32_t bl1 = bl[nt >> 1][(nt & 1) * 2 + 1];
                    mma_bf16(acc[mt][nt], ah, bh0, bh1);
                    mma_bf16(acc[mt][nt], ah, bl0, bl1);
                    mma_bf16(acc[mt][nt], al, bh0, bh1);
                }
            }
        }
        __syncthreads();
    }

    const int er = lane >> 2;
    const int ec = (lane & 3) * 2;

    if (MODE == 0) {
        const int w  = bn >> 11;
        const int ln = (bn & 2047) + wn;
        const float* bias = (w == 0) ? b0 : (w == 1) ? b1 : b2;
        __nv_bfloat16* oh = (w == 0) ? o0h : (w == 1) ? o1h : o2h;
        __nv_bfloat16* ol = (w == 0) ? o0l : (w == 1) ? o1l : o2l;
        #pragma unroll
        for (int mt = 0; mt < 4; mt++) {
            #pragma unroll
            for (int nt = 0; nt < 4; nt++) {
                int row = bm + wm + mt * 16 + er;
                int col = ln + nt * 8 + ec;
                float bb0 = bias[col], bb1 = bias[col + 1];
                uint32_t h, l;
                split_pack(acc[mt][nt][0] + bb0, acc[mt][nt][1] + bb1, h, l);
                *(uint32_t*)&oh[(size_t)row * HD + col] = h;
                *(uint32_t*)&ol[(size_t)row * HD + col] = l;
                split_pack(acc[mt][nt][2] + bb0, acc[mt][nt][3] + bb1, h, l);
                *(uint32_t*)&oh[(size_t)(row + 8) * HD + col] = h;
                *(uint32_t*)&ol[(size_t)(row + 8) * HD + col] = l;
            }
        }
    } else {
        #pragma unroll
        for (int mt = 0; mt < 4; mt++) {
            #pragma unroll
            for (int nt = 0; nt < 4; nt++) {
                int row = bm + wm + mt * 16 + er;
                int col = bn + wn + nt * 8 + ec;
                float bb0 = b0[col], bb1 = b0[col + 1];
                *(float2*)&Cf[(size_t)row * HD + col] =
                    make_float2(acc[mt][nt][0] + bb0, acc[mt][nt][1] + bb1);
                *(float2*)&Cf[(size_t)(row + 8) * HD + col] =
                    make_float2(acc[mt][nt][2] + bb0, acc[mt][nt][3] + bb1);
            }
        }
    }
}

// ---------------------------------------------------------------------------
// Tensor-core flash attention, 16 warps (512 thr), warp-pair split:
// S-phase: half keys per warp; PV-phase: half head-dim per warp.
// Q resident in smem; P round-trips through smem; K/V single-buffered with
// split prefetch (K after S-barrier, V after PV-barrier).
// ---------------------------------------------------------------------------
#define AVP 272                     // K/V/Q smem pitch (256B data + 16 pad)
#define PPI 144                     // P smem pitch (128B data + 16 pad)
#define SQH 0
#define SQL 34816
#define SKH 69632
#define SKL 87040
#define SVH 104448
#define SVL 121856
#define SPH 139264
#define SPL 157696
#define SRM 176128                  // row-max exchange: float[128][2]
#define SRS 177152                  // row-sum exchange: float[128][2]
#define ATTN_SMEM 178176

__global__ __launch_bounds__(512, 1) void attn_mma_kernel(
    const __nv_bfloat16* __restrict__ Qhi, const __nv_bfloat16* __restrict__ Qlo,
    const __nv_bfloat16* __restrict__ Khi, const __nv_bfloat16* __restrict__ Klo,
    const __nv_bfloat16* __restrict__ Vhi, const __nv_bfloat16* __restrict__ Vlo,
    const int* __restrict__ mask,
    __nv_bfloat16* __restrict__ Ahi, __nv_bfloat16* __restrict__ Alo)
{
    extern __shared__ __align__(128) char smem[];
    const uint32_t sbase = smem_to_u32(smem);
    float* redm = (float*)(smem + SRM);
    float* reds = (float*)(smem + SRS);
    const int tid  = threadIdx.x;
    const int wid  = tid >> 5;
    const int lane = tid & 31;
    const int rg = wid >> 1;          // row group 0..7 (16 rows each)
    const int hf = wid & 1;           // key-half (S) / d-half (PV)
    const int q0 = blockIdx.x * 128;
    const int h  = blockIdx.y;
    const int b  = blockIdx.z;
    const int hc = h * DH;

    const int r8 = lane & 7;
    const int g  = lane >> 3;
    const uint32_t a_add  = (uint32_t)(r8 + ((g & 1) ? 8 : 0)) * AVP + ((g & 2) ? 16 : 0);
    const uint32_t ap_add = (uint32_t)(r8 + ((g & 1) ? 8 : 0)) * PPI + ((g & 2) ? 16 : 0);
    const uint32_t b_add  = (uint32_t)(r8 + ((g >= 2) ? 8 : 0)) * AVP + ((g & 1) ? 16 : 0);
    const uint32_t v_add  = (uint32_t)(r8 + ((g & 1) ? 8 : 0)) * AVP + ((g >> 1) ? 16 : 0);

    // ---- stage Q resident (hi+lo) ----
    #pragma unroll
    for (int i = 0; i < 4; i++) {
        int lin = i * 512 + tid;       // 2048 16B-chunks per tensor
        int r = lin >> 4, c = lin & 15;
        size_t gq = (size_t)(b * SQ + q0 + r) * HD + hc + c * 8;
        cp_async16(sbase + SQH + (uint32_t)r * AVP + c * 16, Qhi + gq);
        cp_async16(sbase + SQL + (uint32_t)r * AVP + c * 16, Qlo + gq);
    }
    CP_COMMIT();

    #define LOADK(T) do {                                                        \
        _Pragma("unroll")                                                        \
        for (int _i = 0; _i < 2; _i++) {                                         \
            int _lin = _i * 512 + tid;                                           \
            int _r = _lin >> 4, _c = _lin & 15;                                  \
            size_t _gk = (size_t)(b * SQ + (T) * 64 + _r) * HD + hc + _c * 8;    \
            uint32_t _off = (uint32_t)_r * AVP + _c * 16;                        \
            cp_async16(sbase + SKH + _off, Khi + _gk);                           \
            cp_async16(sbase + SKL + _off, Klo + _gk);                           \
        }                                                                        \
        CP_COMMIT();                                                             \
    } while (0)
    #define LOADV(T) do {                                                        \
        _Pragma("unroll")                                                        \
        for (int _i = 0; _i < 2; _i++) {                                         \
            int _lin = _i * 512 + tid;                                           \
            int _r = _lin >> 4, _c = _lin & 15;                                  \
            size_t _gv = (size_t)(b * SQ + (T) * 64 + _r) * HD + hc + _c * 8;    \
            uint32_t _off = (uint32_t)_r * AVP + _c * 16;                        \
            cp_async16(sbase + SVH + _off, Vhi + _gv);                           \
            cp_async16(sbase + SVL + _off, Vlo + _gv);                           \
        }                                                                        \
        CP_COMMIT();                                                             \
    } while (0)

    LOADK(0);
    LOADV(0);

    float m0 = -1e30f, m1 = -1e30f, l0 = 0.f, l1 = 0.f;
    float o[8][4];
    #pragma unroll
    for (int nt = 0; nt < 8; nt++)
        #pragma unroll
        for (int i = 0; i < 4; i++) o[nt][i] = 0.f;

    const float scale = 0.08838834764831845f;   // 1/sqrt(128)
    const int row0l = 16 * rg + (lane >> 2);    // local rows (0..127)
    const int row1l = row0l + 8;
    const int c2 = (lane & 3) * 2;
    const int* mrow0 = mask + ((size_t)b * SQ + q0 + row0l) * SQ;
    const int* mrow1 = mrow0 + 8 * SQ;

    for (int t = 0; t < SQ / 64; t++) {
        CP_WAIT(1);        // K(t) done (V(t) may be outstanding); t=0: Q also done
        __syncthreads();

        // ---- S = Q K^T for this warp's 32-key half ----
        float s[4][4];
        #pragma unroll
        for (int j = 0; j < 4; j++)
            #pragma unroll
            for (int i = 0; i < 4; i++) s[j][i] = 0.f;

        #pragma unroll
        for (int ks = 0; ks < 8; ks++) {
            uint32_t qh[4], ql[4];
            uint32_t qaddr = (uint32_t)(16 * rg) * AVP + ks * 32 + a_add;
            ldsm_x4(qh[0], qh[1], qh[2], qh[3], sbase + SQH + qaddr);
            ldsm_x4(ql[0], ql[1], ql[2], ql[3], sbase + SQL + qaddr);
            #pragma unroll
            for (int p = 0; p < 2; p++) {
                uint32_t kh[4], kl[4];
                uint32_t kaddr = (uint32_t)(32 * hf + 16 * p) * AVP + ks * 32 + b_add;
                ldsm_x4(kh[0], kh[1], kh[2], kh[3], sbase + SKH + kaddr);
                ldsm_x4(kl[0], kl[1], kl[2], kl[3], sbase + SKL + kaddr);
                mma_bf16(s[2*p],   qh, kh[0], kh[1]);
                mma_bf16(s[2*p],   qh, kl[0], kl[1]);
                mma_bf16(s[2*p],   ql, kh[0], kh[1]);
                mma_bf16(s[2*p+1], qh, kh[2], kh[3]);
                mma_bf16(s[2*p+1], qh, kl[2], kl[3]);
                mma_bf16(s[2*p+1], ql, kh[2], kh[3]);
            }
        }

        // ---- mask + scale + partial row max (32 keys) ----
        const int kb = t * 64 + 32 * hf;
        float mx0 = -1e30f, mx1 = -1e30f;
        #pragma unroll
        for (int j = 0; j < 4; j++) {
            int2 mm0 = *(const int2*)&mrow0[kb + 8*j + c2];
            int2 mm1 = *(const int2*)&mrow1[kb + 8*j + c2];
            s[j][0] = mm0.x ? s[j][0] * scale : -1e30f;
            s[j][1] = mm0.y ? s[j][1] * scale : -1e30f;
            s[j][2] = mm1.x ? s[j][2] * scale : -1e30f;
            s[j][3] = mm1.y ? s[j][3] * scale : -1e30f;
            mx0 = fmaxf(mx0, fmaxf(s[j][0], s[j][1]));
            mx1 = fmaxf(mx1, fmaxf(s[j][2], s[j][3]));
        }
        mx0 = fmaxf(mx0, __shfl_xor_sync(0xffffffffu, mx0, 1));
        mx0 = fmaxf(mx0, __shfl_xor_sync(0xffffffffu, mx0, 2));
        mx1 = fmaxf(mx1, __shfl_xor_sync(0xffffffffu, mx1, 1));
        mx1 = fmaxf(mx1, __shfl_xor_sync(0xffffffffu, mx1, 2));
        if ((lane & 3) == 0) {
            redm[row0l * 2 + hf] = mx0;
            redm[row1l * 2 + hf] = mx1;
        }
        __syncthreads();   // max exchange; all warps done reading K(t)

        if (t + 1 < SQ / 64) LOADK(t + 1);

        float fm0 = fmaxf(redm[row0l * 2], redm[row0l * 2 + 1]);
        float fm1 = fmaxf(redm[row1l * 2], redm[row1l * 2 + 1]);
        float mn0 = fmaxf(m0, fm0), mn1 = fmaxf(m1, fm1);
        float corr0 = __expf(m0 - mn0), corr1 = __expf(m1 - mn1);
        m0 = mn0; m1 = mn1;

        float ps0 = 0.f, ps1 = 0.f;
        #pragma unroll
        for (int j = 0; j < 4; j++) {
            s[j][0] = __expf(s[j][0] - m0);
            s[j][1] = __expf(s[j][1] - m0);
            s[j][2] = __expf(s[j][2] - m1);
            s[j][3] = __expf(s[j][3] - m1);
            ps0 += s[j][0] + s[j][1];
            ps1 += s[j][2] + s[j][3];
        }
        ps0 += __shfl_xor_sync(0xffffffffu, ps0, 1);
        ps0 += __shfl_xor_sync(0xffffffffu, ps0, 2);
        ps1 += __shfl_xor_sync(0xffffffffu, ps1, 1);
        ps1 += __shfl_xor_sync(0xffffffffu, ps1, 2);
        if ((lane & 3) == 0) {
            reds[row0l * 2 + hf] = ps0;
            reds[row1l * 2 + hf] = ps1;
        }

        // ---- write P (bf16 hi/lo) to smem ----
        #pragma unroll
        for (int j = 0; j < 4; j++) {
            int colb = (32 * hf + 8 * j + c2) * 2;
            uint32_t hh, ll;
            split_pack(s[j][0], s[j][1], hh, ll);
            *(uint32_t*)(smem + SPH + row0l * PPI + colb) = hh;
            *(uint32_t*)(smem + SPL + row0l * PPI + colb) = ll;
            split_pack(s[j][2], s[j][3], hh, ll);
            *(uint32_t*)(smem + SPH + row1l * PPI + colb) = hh;
            *(uint32_t*)(smem + SPL + row1l * PPI + colb) = ll;
        }

        if (t + 1 < SQ / 64) { CP_WAIT(1); } else { CP_WAIT(0); }  // V(t) done
        __syncthreads();   // P + sums + V visible

        l0 = l0 * corr0 + ps0 + reds[row0l * 2 + (1 - hf)];
        l1 = l1 * corr1 + ps1 + reds[row1l * 2 + (1 - hf)];
        #pragma unroll
        for (int nt = 0; nt < 8; nt++) {
            o[nt][0] *= corr0; o[nt][1] *= corr0;
            o[nt][2] *= corr1; o[nt][3] *= corr1;
        }

        // ---- O += P V for this warp's 64-d half ----
        #pragma unroll
        for (int ks2 = 0; ks2 < 4; ks2++) {
            uint32_t ph[4], pl[4];
            uint32_t paddr = (uint32_t)(16 * rg) * PPI + ks2 * 32 + ap_add;
            ldsm_x4(ph[0], ph[1], ph[2], ph[3], sbase + SPH + paddr);
            ldsm_x4(pl[0], pl[1], pl[2], pl[3], sbase + SPL + paddr);
            #pragma unroll
            for (int dp = 0; dp < 4; dp++) {
                uint32_t vh[4], vl[4];
                uint32_t vaddr = (uint32_t)(16 * ks2) * AVP + 128 * hf + 32 * dp + v_add;
                ldsm_x4_t(vh[0], vh[1], vh[2], vh[3], sbase + SVH + vaddr);
                ldsm_x4_t(vl[0], vl[1], vl[2], vl[3], sbase + SVL + vaddr);
                mma_bf16(o[2*dp],   ph, vh[0], vh[1]);
                mma_bf16(o[2*dp],   ph, vl[0], vl[1]);
                mma_bf16(o[2*dp],   pl, vh[0], vh[1]);
                mma_bf16(o[2*dp+1], ph, vh[2], vh[3]);
                mma_bf16(o[2*dp+1], ph, vl[2], vl[3]);
                mma_bf16(o[2*dp+1], pl, vh[2], vh[3]);
            }
        }
        __syncthreads();   // all done reading V(t) & P

        if (t + 1 < SQ / 64) LOADV(t + 1);
    }

    // ---- epilogue: normalize, split, store this warp's 64-d half ----
    const float inv0 = 1.f / l0, inv1 = 1.f / l1;
    const size_t ob0 = (size_t)(b * SQ + q0 + row0l) * HD + hc;
    const size_t ob1 = ob0 + (size_t)8 * HD;
    #pragma unroll
    for (int nt = 0; nt < 8; nt++) {
        int col = 64 * hf + 8 * nt + c2;
        uint32_t hh, ll;
        split_pack(o[nt][0] * inv0, o[nt][1] * inv0, hh, ll);
        *(uint32_t*)&Ahi[ob0 + col] = hh;
        *(uint32_t*)&Alo[ob0 + col] = ll;
        split_pack(o[nt][2] * inv1, o[nt][3] * inv1, hh, ll);
        *(uint32_t*)&Ahi[ob1 + col] = hh;
        *(uint32_t*)&Alo[ob1 + col] = ll;
    }
}

// ---------------------------------------------------------------------------

extern "C" void kernel_launch(void* const* d_in, const int* in_sizes, int n_in,
                              void* d_out, int out_size)
{
    const float* X   = (const float*)d_in[0];
    const int*   msk = (const int*)  d_in[1];
    const float* Wq  = (const float*)d_in[2];
    const float* bq  = (const float*)d_in[3];
    const float* Wk  = (const float*)d_in[4];
    const float* bk  = (const float*)d_in[5];
    const float* Wv  = (const float*)d_in[6];
    const float* bv  = (const float*)d_in[7];
    const float* Wo  = (const float*)d_in[8];
    const float* bo  = (const float*)d_in[9];
    float* out = (float*)d_out;

    __nv_bfloat16 *Qhi, *Qlo, *Khi, *Klo, *Vhi, *Vlo, *Ahi, *Alo, *Xhi, *Xlo, *Wthi, *Wtlo;
    cudaGetSymbolAddress((void**)&Qhi, g_Qhi);
    cudaGetSymbolAddress((void**)&Qlo, g_Qlo);
    cudaGetSymbolAddress((void**)&Khi, g_Khi);
    cudaGetSymbolAddress((void**)&Klo, g_Klo);
    cudaGetSymbolAddress((void**)&Vhi, g_Vhi);
    cudaGetSymbolAddress((void**)&Vlo, g_Vlo);
    cudaGetSymbolAddress((void**)&Ahi, g_Ahi);
    cudaGetSymbolAddress((void**)&Alo, g_Alo);
    cudaGetSymbolAddress((void**)&Xhi, g_Xhi);
    cudaGetSymbolAddress((void**)&Xlo, g_Xlo);
    cudaGetSymbolAddress((void**)&Wthi, g_Wthi);
    cudaGetSymbolAddress((void**)&Wtlo, g_Wtlo);

    const size_t WSZ = (size_t)HD * HD;
    const int n4 = MR * HD / 4;

    cudaFuncSetAttribute(gemm_mma_kernel<0>,
                         cudaFuncAttributeMaxDynamicSharedMemorySize, GEMM_SMEM);
    cudaFuncSetAttribute(gemm_mma_kernel<1>,
                         cudaFuncAttributeMaxDynamicSharedMemorySize, GEMM_SMEM);
    cudaFuncSetAttribute(attn_mma_kernel,
                         cudaFuncAttributeMaxDynamicSharedMemorySize, ATTN_SMEM);

    // 1. bf16 hi/lo splits of X; batched weight transpose+split
    cvt_split_kernel<<<n4 / 256, 256>>>((const float4*)X, Xhi, Xlo, n4);
    dim3 wg(HD / 32, HD / 32, 4), wb(32, 8);
    cvt_wt_kernel<<<wg, wb>>>(Wq, Wk, Wv, Wo, Wthi, Wtlo);

    // 2. Fused Q/K/V projection
    dim3 gq(3 * HD / 128, MR / 128);   // (48, 32)
    gemm_mma_kernel<0><<<gq, 256, GEMM_SMEM>>>(
        Xhi, Xlo, Wthi, Wtlo, bq, bk, bv,
        Qhi, Qlo, Khi, Klo, Vhi, Vlo, nullptr);

    // 3. tensor-core flash attention (16 warps)
    dim3 ga(SQ / 128, NH, BB);
    attn_mma_kernel<<<ga, 512, ATTN_SMEM>>>(Qhi, Qlo, Khi, Klo, Vhi, Vlo, msk, Ahi, Alo);

    // 4. output projection -> fp32 out
    dim3 go(HD / 128, MR / 128);       // (16, 32)
    gemm_mma_kernel<1><<<go, 256, GEMM_SMEM>>>(
        Ahi, Alo, Wthi + 3*WSZ, Wtlo + 3*WSZ, bo, bo, bo,
        nullptr, nullptr, nullptr, nullptr, nullptr, nullptr, out);
}

// round 9
// speedup vs baseline: 1.0587x; 1.0587x over previous
#include <cuda_runtime.h>
#include <cuda_bf16.h>
#include <cstdint>

#define HD 2048
#define NH 16
#define DH 128
#define BB 2
#define SQ 2048
#define MR (BB*SQ)   // 4096 rows

// ---------------------------------------------------------------------------
// Scratch (device globals; no allocations allowed)
// ---------------------------------------------------------------------------
__device__ __nv_bfloat16 g_Qhi[(size_t)MR*HD];
__device__ __nv_bfloat16 g_Qlo[(size_t)MR*HD];
__device__ __nv_bfloat16 g_Khi[(size_t)MR*HD];
__device__ __nv_bfloat16 g_Klo[(size_t)MR*HD];
__device__ __nv_bfloat16 g_Vhi[(size_t)MR*HD];
__device__ __nv_bfloat16 g_Vlo[(size_t)MR*HD];
__device__ __nv_bfloat16 g_Ahi[(size_t)MR*HD];
__device__ __nv_bfloat16 g_Alo[(size_t)MR*HD];
__device__ __nv_bfloat16 g_Xhi[(size_t)MR*HD];
__device__ __nv_bfloat16 g_Xlo[(size_t)MR*HD];
__device__ __nv_bfloat16 g_Wthi[4][(size_t)HD*HD];   // transposed: [n][k]; Q,K,V contiguous
__device__ __nv_bfloat16 g_Wtlo[4][(size_t)HD*HD];

// ---------------------------------------------------------------------------
// PTX helpers (compute_103-safe: mma.sync / ldmatrix / cp.async only)
// ---------------------------------------------------------------------------
__device__ __forceinline__ uint32_t smem_to_u32(const void* p) {
    uint32_t a;
    asm("{ .reg .u64 t; cvta.to.shared.u64 t, %1; cvt.u32.u64 %0, t; }"
        : "=r"(a) : "l"(p));
    return a;
}
__device__ __forceinline__ void cp_async16(uint32_t s, const void* g) {
    asm volatile("cp.async.cg.shared.global [%0], [%1], 16;" :: "r"(s), "l"(g));
}
#define CP_COMMIT() asm volatile("cp.async.commit_group;" ::: "memory")
#define CP_WAIT(n)  asm volatile("cp.async.wait_group %0;" :: "n"(n) : "memory")

__device__ __forceinline__ void ldsm_x4(uint32_t& r0, uint32_t& r1,
                                        uint32_t& r2, uint32_t& r3, uint32_t addr) {
    asm volatile("ldmatrix.sync.aligned.m8n8.x4.shared.b16 {%0,%1,%2,%3}, [%4];"
        : "=r"(r0), "=r"(r1), "=r"(r2), "=r"(r3) : "r"(addr));
}
__device__ __forceinline__ void ldsm_x4_t(uint32_t& r0, uint32_t& r1,
                                          uint32_t& r2, uint32_t& r3, uint32_t addr) {
    asm volatile("ldmatrix.sync.aligned.m8n8.x4.trans.shared.b16 {%0,%1,%2,%3}, [%4];"
        : "=r"(r0), "=r"(r1), "=r"(r2), "=r"(r3) : "r"(addr));
}
__device__ __forceinline__ void mma_bf16(float* c, const uint32_t* a,
                                         uint32_t b0, uint32_t b1) {
    asm volatile(
        "mma.sync.aligned.m16n8k16.row.col.f32.bf16.bf16.f32 "
        "{%0,%1,%2,%3}, {%4,%5,%6,%7}, {%8,%9}, {%0,%1,%2,%3};"
        : "+f"(c[0]), "+f"(c[1]), "+f"(c[2]), "+f"(c[3])
        : "r"(a[0]), "r"(a[1]), "r"(a[2]), "r"(a[3]), "r"(b0), "r"(b1));
}
__device__ __forceinline__ uint32_t pack_bf2(__nv_bfloat16 a, __nv_bfloat16 b) {
    __nv_bfloat162 t(a, b);
    return *(uint32_t*)&t;
}
__device__ __forceinline__ void split_pack(float x, float y, uint32_t& hi, uint32_t& lo) {
    __nv_bfloat16 hx = __float2bfloat16(x);
    __nv_bfloat16 hy = __float2bfloat16(y);
    __nv_bfloat16 lx = __float2bfloat16(x - __bfloat162float(hx));
    __nv_bfloat16 ly = __float2bfloat16(y - __bfloat162float(hy));
    hi = pack_bf2(hx, hy);
    lo = pack_bf2(lx, ly);
}

// ---------------------------------------------------------------------------
// Conversion kernels (unchanged)
// ---------------------------------------------------------------------------
__global__ __launch_bounds__(256) void cvt_split_kernel(
    const float4* __restrict__ in, __nv_bfloat16* __restrict__ hi,
    __nv_bfloat16* __restrict__ lo, int n4)
{
    int i = blockIdx.x * 256 + threadIdx.x;
    if (i >= n4) return;
    float4 v = in[i];
    float f[4] = {v.x, v.y, v.z, v.w};
    #pragma unroll
    for (int p = 0; p < 2; p++) {
        uint32_t h, l;
        split_pack(f[2*p+0], f[2*p+1], h, l);
        ((uint32_t*)hi)[2*i+p] = h;
        ((uint32_t*)lo)[2*i+p] = l;
    }
}

__global__ __launch_bounds__(256) void cvt_wt_kernel(
    const float* __restrict__ W0, const float* __restrict__ W1,
    const float* __restrict__ W2, const float* __restrict__ W3,
    __nv_bfloat16* __restrict__ hib, __nv_bfloat16* __restrict__ lob)
{
    __shared__ float tile[32][33];
    const int z = blockIdx.z;
    const float* W = (z == 0) ? W0 : (z == 1) ? W1 : (z == 2) ? W2 : W3;
    __nv_bfloat16* hi = hib + (size_t)z * HD * HD;
    __nv_bfloat16* lo = lob + (size_t)z * HD * HD;
    const int n0 = blockIdx.x * 32, k0 = blockIdx.y * 32;
    const int tx = threadIdx.x, ty = threadIdx.y;
    #pragma unroll
    for (int i = 0; i < 4; i++)
        tile[ty + 8*i][tx] = W[(size_t)(k0 + ty + 8*i) * HD + n0 + tx];
    __syncthreads();
    #pragma unroll
    for (int i = 0; i < 4; i++) {
        float v = tile[tx][ty + 8*i];
        __nv_bfloat16 h = __float2bfloat16(v);
        __nv_bfloat16 l = __float2bfloat16(v - __bfloat162float(h));
        size_t idx = (size_t)(n0 + ty + 8*i) * HD + k0 + tx;
        hi[idx] = h;
        lo[idx] = l;
    }
}

// ---------------------------------------------------------------------------
// mma.sync GEMM (unchanged from round 7)
// ---------------------------------------------------------------------------
#define KC 32
#define PITCHB 80
#define TILE_BYTES (128 * PITCHB)
#define STAGE_BYTES (4 * TILE_BYTES)
#define GEMM_SMEM (2 * STAGE_BYTES)     // 81920

template<int MODE>
__global__ __launch_bounds__(256, 2) void gemm_mma_kernel(
    const __nv_bfloat16* __restrict__ Ahi, const __nv_bfloat16* __restrict__ Alo,
    const __nv_bfloat16* __restrict__ Bhi, const __nv_bfloat16* __restrict__ Blo,
    const float* __restrict__ b0, const float* __restrict__ b1,
    const float* __restrict__ b2,
    __nv_bfloat16* __restrict__ o0h, __nv_bfloat16* __restrict__ o0l,
    __nv_bfloat16* __restrict__ o1h, __nv_bfloat16* __restrict__ o1l,
    __nv_bfloat16* __restrict__ o2h, __nv_bfloat16* __restrict__ o2l,
    float* __restrict__ Cf)
{
    extern __shared__ __align__(128) char smem[];
    const uint32_t sbase = smem_to_u32(smem);
    const int tid  = threadIdx.x;
    const int wid  = tid >> 5;
    const int lane = tid & 31;
    const int bm = blockIdx.y * 128;
    const int bn = blockIdx.x * 128;
    const int wm = (wid >> 2) * 64;
    const int wn = (wid & 3) * 32;

    float acc[4][4][4];
    #pragma unroll
    for (int mt = 0; mt < 4; mt++)
        #pragma unroll
        for (int nt = 0; nt < 4; nt++)
            #pragma unroll
            for (int i = 0; i < 4; i++) acc[mt][nt][i] = 0.f;

    const int lr = tid >> 2;
    const int lc = tid & 3;

    {
        const uint32_t sb = sbase;
        #pragma unroll
        for (int i = 0; i < 2; i++) {
            int r = lr + i * 64;
            uint32_t off = (uint32_t)r * PITCHB + lc * 16;
            size_t ga = (size_t)(bm + r) * HD + lc * 8;
            size_t gb = (size_t)(bn + r) * HD + lc * 8;
            cp_async16(sb + 0*TILE_BYTES + off, Ahi + ga);
            cp_async16(sb + 1*TILE_BYTES + off, Alo + ga);
            cp_async16(sb + 2*TILE_BYTES + off, Bhi + gb);
            cp_async16(sb + 3*TILE_BYTES + off, Blo + gb);
        }
        CP_COMMIT();
    }

    const int r8 = lane & 7;
    const int g  = lane >> 3;
    const uint32_t a_row_add = (uint32_t)(r8 + ((g & 1) ? 8 : 0)) * PITCHB + ((g & 2) ? 16 : 0);
    const uint32_t b_row_add = (uint32_t)(r8 + ((g >= 2) ? 8 : 0)) * PITCHB + ((g & 1) ? 16 : 0);

    for (int t = 0; t < HD / KC; t++) {
        if (t + 1 < HD / KC) {
            const int k0 = (t + 1) * KC;
            const uint32_t sb = sbase + ((t + 1) & 1) * STAGE_BYTES;
            #pragma unroll
            for (int i = 0; i < 2; i++) {
                int r = lr + i * 64;
                uint32_t off = (uint32_t)r * PITCHB + lc * 16;
                size_t ga = (size_t)(bm + r) * HD + k0 + lc * 8;
                size_t gb = (size_t)(bn + r) * HD + k0 + lc * 8;
                cp_async16(sb + 0*TILE_BYTES + off, Ahi + ga);
                cp_async16(sb + 1*TILE_BYTES + off, Alo + ga);
                cp_async16(sb + 2*TILE_BYTES + off, Bhi + gb);
                cp_async16(sb + 3*TILE_BYTES + off, Blo + gb);
            }
            CP_COMMIT();
            CP_WAIT(1);
        } else {
            CP_WAIT(0);
        }
        __syncthreads();

        const uint32_t sb = sbase + (t & 1) * STAGE_BYTES;
        #pragma unroll
        for (int ks = 0; ks < 2; ks++) {
            uint32_t bh[2][4], bl[2][4];
            #pragma unroll
            for (int p = 0; p < 2; p++) {
                uint32_t addr = sb + (uint32_t)(wn + p * 16) * PITCHB + ks * 32 + b_row_add;
                ldsm_x4(bh[p][0], bh[p][1], bh[p][2], bh[p][3], addr + 2*TILE_BYTES);
                ldsm_x4(bl[p][0], bl[p][1], bl[p][2], bl[p][3], addr + 3*TILE_BYTES);
            }
            #pragma unroll
            for (int mt = 0; mt < 4; mt++) {
                uint32_t ah[4], al[4];
                uint32_t addr = sb + (uint32_t)(wm + mt * 16) * PITCHB + ks * 32 + a_row_add;
                ldsm_x4(ah[0], ah[1], ah[2], ah[3], addr + 0*TILE_BYTES);
                ldsm_x4(al[0], al[1], al[2], al[3], addr + 1*TILE_BYTES);
                #pragma unroll
                for (int nt = 0; nt < 4; nt++) {
                    uint32_t bh0 = bh[nt >> 1][(nt & 1) * 2 + 0];
                    uint32_t bh1 = bh[nt >> 1][(nt & 1) * 2 + 1];
                    uint32_t bl0 = bl[nt >> 1][(nt & 1) * 2 + 0];
                    uint32_t bl1 = bl[nt >> 1][(nt & 1) * 2 + 1];
                    mma_bf16(acc[mt][nt], ah, bh0, bh1);
                    mma_bf16(acc[mt][nt], ah, bl0, bl1);
                    mma_bf16(acc[mt][nt], al, bh0, bh1);
                }
            }
        }
        __syncthreads();
    }

    const int er = lane >> 2;
    const int ec = (lane & 3) * 2;

    if (MODE == 0) {
        const int w  = bn >> 11;
        const int ln = (bn & 2047) + wn;
        const float* bias = (w == 0) ? b0 : (w == 1) ? b1 : b2;
        __nv_bfloat16* oh = (w == 0) ? o0h : (w == 1) ? o1h : o2h;
        __nv_bfloat16* ol = (w == 0) ? o0l : (w == 1) ? o1l : o2l;
        #pragma unroll
        for (int mt = 0; mt < 4; mt++) {
            #pragma unroll
            for (int nt = 0; nt < 4; nt++) {
                int row = bm + wm + mt * 16 + er;
                int col = ln + nt * 8 + ec;
                float bb0 = bias[col], bb1 = bias[col + 1];
                uint32_t h, l;
                split_pack(acc[mt][nt][0] + bb0, acc[mt][nt][1] + bb1, h, l);
                *(uint32_t*)&oh[(size_t)row * HD + col] = h;
                *(uint32_t*)&ol[(size_t)row * HD + col] = l;
                split_pack(acc[mt][nt][2] + bb0, acc[mt][nt][3] + bb1, h, l);
                *(uint32_t*)&oh[(size_t)(row + 8) * HD + col] = h;
                *(uint32_t*)&ol[(size_t)(row + 8) * HD + col] = l;
            }
        }
    } else {
        #pragma unroll
        for (int mt = 0; mt < 4; mt++) {
            #pragma unroll
            for (int nt = 0; nt < 4; nt++) {
                int row = bm + wm + mt * 16 + er;
                int col = bn + wn + nt * 8 + ec;
                float bb0 = b0[col], bb1 = b0[col + 1];
                *(float2*)&Cf[(size_t)row * HD + col] =
                    make_float2(acc[mt][nt][0] + bb0, acc[mt][nt][1] + bb1);
                *(float2*)&Cf[(size_t)(row + 8) * HD + col] =
                    make_float2(acc[mt][nt][2] + bb0, acc[mt][nt][3] + bb1);
            }
        }
    }
}

// ---------------------------------------------------------------------------
// Tensor-core flash attention — round-7 structure, half-size CTA for 2 CTAs/SM.
// CTA: 4 warps, 64 q-rows; warp = 16 rows x full 32-key chunk (private softmax,
// no intra-chunk barriers). Q in registers. K/V hi/lo double-buffered (69.6KB).
// ---------------------------------------------------------------------------
#define AVP 272                     // smem pitch bytes (256 data + 16 pad)
#define KTB32 (32 * AVP)            // 8704 per tensor tile (32 rows)
#define STB32 (4 * KTB32)           // 34816 per stage (Khi,Klo,Vhi,Vlo)
#define ATTN_SMEM (2 * STB32)       // 69632
#define QSTG_H 0                    // Q staged in stage-0 area (freed before loop)
#define QSTG_L (64 * AVP)           // 17408

__global__ __launch_bounds__(128, 2) void attn_mma_kernel(
    const __nv_bfloat16* __restrict__ Qhi, const __nv_bfloat16* __restrict__ Qlo,
    const __nv_bfloat16* __restrict__ Khi, const __nv_bfloat16* __restrict__ Klo,
    const __nv_bfloat16* __restrict__ Vhi, const __nv_bfloat16* __restrict__ Vlo,
    const int* __restrict__ mask,
    __nv_bfloat16* __restrict__ Ahi, __nv_bfloat16* __restrict__ Alo)
{
    extern __shared__ __align__(128) char smem[];
    const uint32_t sbase = smem_to_u32(smem);
    const int tid  = threadIdx.x;
    const int wid  = tid >> 5;          // 0..3
    const int lane = tid & 31;
    const int q0 = blockIdx.x * 64;
    const int h  = blockIdx.y;
    const int b  = blockIdx.z;
    const int hc = h * DH;

    const int r8 = lane & 7;
    const int g  = lane >> 3;
    const uint32_t a_add = (uint32_t)(r8 + ((g & 1) ? 8 : 0)) * AVP + ((g & 2) ? 16 : 0);
    const uint32_t b_add = (uint32_t)(r8 + ((g >= 2) ? 8 : 0)) * AVP + ((g & 1) ? 16 : 0);
    const uint32_t v_add = (uint32_t)(r8 + ((g & 1) ? 8 : 0)) * AVP + ((g >> 1) ? 16 : 0);

    // ---- stage Q tile (64 x 128 d, hi+lo) into stage-0 area; load A-frags ----
    {
        #pragma unroll
        for (int i = 0; i < 8; i++) {
            int lin = i * 128 + tid;       // 1024 16B-chunks per tensor
            int r = lin >> 4, c = lin & 15;
            size_t gq = (size_t)(b * SQ + q0 + r) * HD + hc + c * 8;
            cp_async16(sbase + QSTG_H + (uint32_t)r * AVP + c * 16, Qhi + gq);
            cp_async16(sbase + QSTG_L + (uint32_t)r * AVP + c * 16, Qlo + gq);
        }
        CP_COMMIT();
        CP_WAIT(0);
        __syncthreads();
    }

    uint32_t qh[8][4], ql[8][4];
    #pragma unroll
    for (int ks = 0; ks < 8; ks++) {
        uint32_t addr = (uint32_t)(16 * wid) * AVP + ks * 32 + a_add;
        ldsm_x4(qh[ks][0], qh[ks][1], qh[ks][2], qh[ks][3], sbase + QSTG_H + addr);
        ldsm_x4(ql[ks][0], ql[ks][1], ql[ks][2], ql[ks][3], sbase + QSTG_L + addr);
    }
    __syncthreads();   // Q staging area now reusable as K/V stage 0

    #define LOAD_CHUNK32(T, STAGE) do {                                          \
        const uint32_t _sb = sbase + (STAGE) * STB32;                            \
        _Pragma("unroll")                                                        \
        for (int _i = 0; _i < 4; _i++) {                                         \
            int _lin = _i * 128 + tid;        /* 512 16B-chunks per tensor */    \
            int _r = _lin >> 4, _c = _lin & 15;                                  \
            size_t _gk = (size_t)(b * SQ + (T) * 32 + _r) * HD + hc + _c * 8;    \
            uint32_t _off = (uint32_t)_r * AVP + _c * 16;                        \
            cp_async16(_sb + 0*KTB32 + _off, Khi + _gk);                         \
            cp_async16(_sb + 1*KTB32 + _off, Klo + _gk);                         \
            cp_async16(_sb + 2*KTB32 + _off, Vhi + _gk);                         \
            cp_async16(_sb + 3*KTB32 + _off, Vlo + _gk);                         \
        }                                                                        \
        CP_COMMIT();                                                             \
    } while (0)

    LOAD_CHUNK32(0, 0);

    float m0 = -1e30f, m1 = -1e30f, l0 = 0.f, l1 = 0.f;
    float o[16][4];
    #pragma unroll
    for (int nt = 0; nt < 16; nt++)
        #pragma unroll
        for (int i = 0; i < 4; i++) o[nt][i] = 0.f;

    const float scale = 0.08838834764831845f;   // 1/sqrt(128)
    const int row0 = q0 + 16 * wid + (lane >> 2);
    const int c2 = (lane & 3) * 2;
    const int* mrow0 = mask + ((size_t)b * SQ + row0) * SQ;
    const int* mrow1 = mrow0 + 8 * SQ;

    for (int t = 0; t < SQ / 32; t++) {
        if (t + 1 < SQ / 32) { LOAD_CHUNK32(t + 1, (t + 1) & 1); CP_WAIT(1); }
        else CP_WAIT(0);
        __syncthreads();

        const uint32_t sb = sbase + (t & 1) * STB32;

        // ---- S = Q K^T over 32 keys ----
        float s[4][4];
        #pragma unroll
        for (int j = 0; j < 4; j++)
            #pragma unroll
            for (int i = 0; i < 4; i++) s[j][i] = 0.f;

        #pragma unroll
        for (int ks = 0; ks < 8; ks++) {
            #pragma unroll
            for (int p = 0; p < 2; p++) {
                uint32_t kh[4], kl[4];
                uint32_t addr = sb + (uint32_t)(16 * p) * AVP + ks * 32 + b_add;
                ldsm_x4(kh[0], kh[1], kh[2], kh[3], addr + 0*KTB32);
                ldsm_x4(kl[0], kl[1], kl[2], kl[3], addr + 1*KTB32);
                mma_bf16(s[2*p],   qh[ks], kh[0], kh[1]);
                mma_bf16(s[2*p],   qh[ks], kl[0], kl[1]);
                mma_bf16(s[2*p],   ql[ks], kh[0], kh[1]);
                mma_bf16(s[2*p+1], qh[ks], kh[2], kh[3]);
                mma_bf16(s[2*p+1], qh[ks], kl[2], kl[3]);
                mma_bf16(s[2*p+1], ql[ks], kh[2], kh[3]);
            }
        }

        // ---- mask + scale + online softmax (warp-private) ----
        const int k0 = t * 32;
        float mx0 = -1e30f, mx1 = -1e30f;
        #pragma unroll
        for (int j = 0; j < 4; j++) {
            int2 mm0 = *(const int2*)&mrow0[k0 + 8*j + c2];
            int2 mm1 = *(const int2*)&mrow1[k0 + 8*j + c2];
            s[j][0] = mm0.x ? s[j][0] * scale : -1e30f;
            s[j][1] = mm0.y ? s[j][1] * scale : -1e30f;
            s[j][2] = mm1.x ? s[j][2] * scale : -1e30f;
            s[j][3] = mm1.y ? s[j][3] * scale : -1e30f;
            mx0 = fmaxf(mx0, fmaxf(s[j][0], s[j][1]));
            mx1 = fmaxf(mx1, fmaxf(s[j][2], s[j][3]));
        }
        mx0 = fmaxf(mx0, __shfl_xor_sync(0xffffffffu, mx0, 1));
        mx0 = fmaxf(mx0, __shfl_xor_sync(0xffffffffu, mx0, 2));
        mx1 = fmaxf(mx1, __shfl_xor_sync(0xffffffffu, mx1, 1));
        mx1 = fmaxf(mx1, __shfl_xor_sync(0xffffffffu, mx1, 2));

        float mn0 = fmaxf(m0, mx0), mn1 = fmaxf(m1, mx1);
        float corr0 = __expf(m0 - mn0), corr1 = __expf(m1 - mn1);
        m0 = mn0; m1 = mn1;

        float ps0 = 0.f, ps1 = 0.f;
        #pragma unroll
        for (int j = 0; j < 4; j++) {
            s[j][0] = __expf(s[j][0] - m0);
            s[j][1] = __expf(s[j][1] - m0);
            s[j][2] = __expf(s[j][2] - m1);
            s[j][3] = __expf(s[j][3] - m1);
            ps0 += s[j][0] + s[j][1];
            ps1 += s[j][2] + s[j][3];
        }
        ps0 += __shfl_xor_sync(0xffffffffu, ps0, 1);
        ps0 += __shfl_xor_sync(0xffffffffu, ps0, 2);
        ps1 += __shfl_xor_sync(0xffffffffu, ps1, 1);
        ps1 += __shfl_xor_sync(0xffffffffu, ps1, 2);
        l0 = l0 * corr0 + ps0;
        l1 = l1 * corr1 + ps1;

        #pragma unroll
        for (int nt = 0; nt < 16; nt++) {
            o[nt][0] *= corr0; o[nt][1] *= corr0;
            o[nt][2] *= corr1; o[nt][3] *= corr1;
        }

        // ---- O += P V (2 k-frags of 16 keys) ----
        #pragma unroll
        for (int ks2 = 0; ks2 < 2; ks2++) {
            uint32_t ph[4], pl[4];
            split_pack(s[2*ks2][0],   s[2*ks2][1],   ph[0], pl[0]);
            split_pack(s[2*ks2][2],   s[2*ks2][3],   ph[1], pl[1]);
            split_pack(s[2*ks2+1][0], s[2*ks2+1][1], ph[2], pl[2]);
            split_pack(s[2*ks2+1][2], s[2*ks2+1][3], ph[3], pl[3]);
            #pragma unroll
            for (int dp = 0; dp < 8; dp++) {
                uint32_t vh[4], vl[4];
                uint32_t addr = sb + (uint32_t)(16 * ks2) * AVP + dp * 32 + v_add;
                ldsm_x4_t(vh[0], vh[1], vh[2], vh[3], addr + 2*KTB32);
                ldsm_x4_t(vl[0], vl[1], vl[2], vl[3], addr + 3*KTB32);
                mma_bf16(o[2*dp],   ph, vh[0], vh[1]);
                mma_bf16(o[2*dp],   ph, vl[0], vl[1]);
                mma_bf16(o[2*dp],   pl, vh[0], vh[1]);
                mma_bf16(o[2*dp+1], ph, vh[2], vh[3]);
                mma_bf16(o[2*dp+1], ph, vl[2], vl[3]);
                mma_bf16(o[2*dp+1], pl, vh[2], vh[3]);
            }
        }
        __syncthreads();
    }

    // ---- epilogue: normalize and store split bf16 ----
    const float inv0 = 1.f / l0, inv1 = 1.f / l1;
    const size_t ob0 = (size_t)(b * SQ + row0) * HD + hc;
    const size_t ob1 = ob0 + (size_t)8 * HD;
    #pragma unroll
    for (int nt = 0; nt < 16; nt++) {
        int col = 8 * nt + c2;
        uint32_t hh, ll;
        split_pack(o[nt][0] * inv0, o[nt][1] * inv0, hh, ll);
        *(uint32_t*)&Ahi[ob0 + col] = hh;
        *(uint32_t*)&Alo[ob0 + col] = ll;
        split_pack(o[nt][2] * inv1, o[nt][3] * inv1, hh, ll);
        *(uint32_t*)&Ahi[ob1 + col] = hh;
        *(uint32_t*)&Alo[ob1 + col] = ll;
    }
}

// ---------------------------------------------------------------------------

extern "C" void kernel_launch(void* const* d_in, const int* in_sizes, int n_in,
                              void* d_out, int out_size)
{
    const float* X   = (const float*)d_in[0];
    const int*   msk = (const int*)  d_in[1];
    const float* Wq  = (const float*)d_in[2];
    const float* bq  = (const float*)d_in[3];
    const float* Wk  = (const float*)d_in[4];
    const float* bk  = (const float*)d_in[5];
    const float* Wv  = (const float*)d_in[6];
    const float* bv  = (const float*)d_in[7];
    const float* Wo  = (const float*)d_in[8];
    const float* bo  = (const float*)d_in[9];
    float* out = (float*)d_out;

    __nv_bfloat16 *Qhi, *Qlo, *Khi, *Klo, *Vhi, *Vlo, *Ahi, *Alo, *Xhi, *Xlo, *Wthi, *Wtlo;
    cudaGetSymbolAddress((void**)&Qhi, g_Qhi);
    cudaGetSymbolAddress((void**)&Qlo, g_Qlo);
    cudaGetSymbolAddress((void**)&Khi, g_Khi);
    cudaGetSymbolAddress((void**)&Klo, g_Klo);
    cudaGetSymbolAddress((void**)&Vhi, g_Vhi);
    cudaGetSymbolAddress((void**)&Vlo, g_Vlo);
    cudaGetSymbolAddress((void**)&Ahi, g_Ahi);
    cudaGetSymbolAddress((void**)&Alo, g_Alo);
    cudaGetSymbolAddress((void**)&Xhi, g_Xhi);
    cudaGetSymbolAddress((void**)&Xlo, g_Xlo);
    cudaGetSymbolAddress((void**)&Wthi, g_Wthi);
    cudaGetSymbolAddress((void**)&Wtlo, g_Wtlo);

    const size_t WSZ = (size_t)HD * HD;
    const int n4 = MR * HD / 4;

    cudaFuncSetAttribute(gemm_mma_kernel<0>,
                         cudaFuncAttributeMaxDynamicSharedMemorySize, GEMM_SMEM);
    cudaFuncSetAttribute(gemm_mma_kernel<1>,
                         cudaFuncAttributeMaxDynamicSharedMemorySize, GEMM_SMEM);
    cudaFuncSetAttribute(attn_mma_kernel,
                         cudaFuncAttributeMaxDynamicSharedMemorySize, ATTN_SMEM);

    // 1. bf16 hi/lo splits of X; batched weight transpose+split
    cvt_split_kernel<<<n4 / 256, 256>>>((const float4*)X, Xhi, Xlo, n4);
    dim3 wg(HD / 32, HD / 32, 4), wb(32, 8);
    cvt_wt_kernel<<<wg, wb>>>(Wq, Wk, Wv, Wo, Wthi, Wtlo);

    // 2. Fused Q/K/V projection
    dim3 gq(3 * HD / 128, MR / 128);   // (48, 32)
    gemm_mma_kernel<0><<<gq, 256, GEMM_SMEM>>>(
        Xhi, Xlo, Wthi, Wtlo, bq, bk, bv,
        Qhi, Qlo, Khi, Klo, Vhi, Vlo, nullptr);

    // 3. tensor-core flash attention (4 warps, 2 CTAs/SM)
    dim3 ga(SQ / 64, NH, BB);          // (32, 16, 2) = 1024 CTAs
    attn_mma_kernel<<<ga, 128, ATTN_SMEM>>>(Qhi, Qlo, Khi, Klo, Vhi, Vlo, msk, Ahi, Alo);

    // 4. output projection -> fp32 out
    dim3 go(HD / 128, MR / 128);       // (16, 32)
    gemm_mma_kernel<1><<<go, 256, GEMM_SMEM>>>(
        Ahi, Alo, Wthi + 3*WSZ, Wtlo + 3*WSZ, bo, bo, bo,
        nullptr, nullptr, nullptr, nullptr, nullptr, nullptr, out);
}

// round 10
// speedup vs baseline: 1.3405x; 1.2662x over previous
#include <cuda_runtime.h>
#include <cuda_bf16.h>
#include <cuda_fp16.h>
#include <cstdint>

#define HD 2048
#define NH 16
#define DH 128
#define BB 2
#define SQ 2048
#define MR (BB*SQ)   // 4096 rows

// ---------------------------------------------------------------------------
// Scratch (device globals; no allocations allowed)
// ---------------------------------------------------------------------------
__device__ __nv_bfloat16 g_Qhi[(size_t)MR*HD];
__device__ __nv_bfloat16 g_Qlo[(size_t)MR*HD];
__device__ __nv_bfloat16 g_Khi[(size_t)MR*HD];
__device__ __nv_bfloat16 g_Klo[(size_t)MR*HD];
__device__ __nv_bfloat16 g_Vhi[(size_t)MR*HD];
__device__ __nv_bfloat16 g_Vlo[(size_t)MR*HD];
__device__ __half g_Ahi[(size_t)MR*HD];
__device__ __half g_Alo[(size_t)MR*HD];
__device__ __half g_Xhi[(size_t)MR*HD];
__device__ __half g_Xlo[(size_t)MR*HD];
__device__ __half g_Wt[4][(size_t)HD*HD];    // transposed [n][k], single fp16; Q,K,V contiguous

// ---------------------------------------------------------------------------
// PTX helpers (compute_103-safe)
// ---------------------------------------------------------------------------
__device__ __forceinline__ uint32_t smem_to_u32(const void* p) {
    uint32_t a;
    asm("{ .reg .u64 t; cvta.to.shared.u64 t, %1; cvt.u32.u64 %0, t; }"
        : "=r"(a) : "l"(p));
    return a;
}
__device__ __forceinline__ void cp_async16(uint32_t s, const void* g) {
    asm volatile("cp.async.cg.shared.global [%0], [%1], 16;" :: "r"(s), "l"(g));
}
#define CP_COMMIT() asm volatile("cp.async.commit_group;" ::: "memory")
#define CP_WAIT(n)  asm volatile("cp.async.wait_group %0;" :: "n"(n) : "memory")

__device__ __forceinline__ void ldsm_x4(uint32_t& r0, uint32_t& r1,
                                        uint32_t& r2, uint32_t& r3, uint32_t addr) {
    asm volatile("ldmatrix.sync.aligned.m8n8.x4.shared.b16 {%0,%1,%2,%3}, [%4];"
        : "=r"(r0), "=r"(r1), "=r"(r2), "=r"(r3) : "r"(addr));
}
__device__ __forceinline__ void ldsm_x4_t(uint32_t& r0, uint32_t& r1,
                                          uint32_t& r2, uint32_t& r3, uint32_t addr) {
    asm volatile("ldmatrix.sync.aligned.m8n8.x4.trans.shared.b16 {%0,%1,%2,%3}, [%4];"
        : "=r"(r0), "=r"(r1), "=r"(r2), "=r"(r3) : "r"(addr));
}
__device__ __forceinline__ void mma_bf16(float* c, const uint32_t* a,
                                         uint32_t b0, uint32_t b1) {
    asm volatile(
        "mma.sync.aligned.m16n8k16.row.col.f32.bf16.bf16.f32 "
        "{%0,%1,%2,%3}, {%4,%5,%6,%7}, {%8,%9}, {%0,%1,%2,%3};"
        : "+f"(c[0]), "+f"(c[1]), "+f"(c[2]), "+f"(c[3])
        : "r"(a[0]), "r"(a[1]), "r"(a[2]), "r"(a[3]), "r"(b0), "r"(b1));
}
__device__ __forceinline__ void mma_f16(float* c, const uint32_t* a,
                                        uint32_t b0, uint32_t b1) {
    asm volatile(
        "mma.sync.aligned.m16n8k16.row.col.f32.f16.f16.f32 "
        "{%0,%1,%2,%3}, {%4,%5,%6,%7}, {%8,%9}, {%0,%1,%2,%3};"
        : "+f"(c[0]), "+f"(c[1]), "+f"(c[2]), "+f"(c[3])
        : "r"(a[0]), "r"(a[1]), "r"(a[2]), "r"(a[3]), "r"(b0), "r"(b1));
}
__device__ __forceinline__ float ex2(float x) {
    float y;
    asm("ex2.approx.ftz.f32 %0, %1;" : "=f"(y) : "f"(x));
    return y;
}
__device__ __forceinline__ uint32_t pack_bf2(__nv_bfloat16 a, __nv_bfloat16 b) {
    __nv_bfloat162 t(a, b);
    return *(uint32_t*)&t;
}
// fp32 pair -> bf16 hi + bf16 residual (for attention inputs)
__device__ __forceinline__ void split_pack(float x, float y, uint32_t& hi, uint32_t& lo) {
    __nv_bfloat16 hx = __float2bfloat16(x);
    __nv_bfloat16 hy = __float2bfloat16(y);
    __nv_bfloat16 lx = __float2bfloat16(x - __bfloat162float(hx));
    __nv_bfloat16 ly = __float2bfloat16(y - __bfloat162float(hy));
    hi = pack_bf2(hx, hy);
    lo = pack_bf2(lx, ly);
}
// fp32 pair -> fp16 hi + fp16 residual (for GEMM A-operands)
__device__ __forceinline__ void split_pack_h(float x, float y, uint32_t& hi, uint32_t& lo) {
    __half hx = __float2half_rn(x);
    __half hy = __float2half_rn(y);
    __half lx = __float2half_rn(x - __half2float(hx));
    __half ly = __float2half_rn(y - __half2float(hy));
    __half2 h(hx, hy), l(lx, ly);
    hi = *(uint32_t*)&h;
    lo = *(uint32_t*)&l;
}

// ---------------------------------------------------------------------------
// Conversion kernels
// ---------------------------------------------------------------------------
__global__ __launch_bounds__(256) void cvt_split_h_kernel(
    const float4* __restrict__ in, __half* __restrict__ hi,
    __half* __restrict__ lo, int n4)
{
    int i = blockIdx.x * 256 + threadIdx.x;
    if (i >= n4) return;
    float4 v = in[i];
    float f[4] = {v.x, v.y, v.z, v.w};
    #pragma unroll
    for (int p = 0; p < 2; p++) {
        uint32_t h, l;
        split_pack_h(f[2*p+0], f[2*p+1], h, l);
        ((uint32_t*)hi)[2*i+p] = h;
        ((uint32_t*)lo)[2*i+p] = l;
    }
}

// Batched: W[K,N] fp32 -> Wt[n][k] single fp16. blockIdx.z selects weight.
__global__ __launch_bounds__(256) void cvt_wt_kernel(
    const float* __restrict__ W0, const float* __restrict__ W1,
    const float* __restrict__ W2, const float* __restrict__ W3,
    __half* __restrict__ outb)
{
    __shared__ float tile[32][33];
    const int z = blockIdx.z;
    const float* W = (z == 0) ? W0 : (z == 1) ? W1 : (z == 2) ? W2 : W3;
    __half* o = outb + (size_t)z * HD * HD;
    const int n0 = blockIdx.x * 32, k0 = blockIdx.y * 32;
    const int tx = threadIdx.x, ty = threadIdx.y;
    #pragma unroll
    for (int i = 0; i < 4; i++)
        tile[ty + 8*i][tx] = W[(size_t)(k0 + ty + 8*i) * HD + n0 + tx];
    __syncthreads();
    #pragma unroll
    for (int i = 0; i < 4; i++) {
        float v = tile[tx][ty + 8*i];
        o[(size_t)(n0 + ty + 8*i) * HD + k0 + tx] = __float2half_rn(v);
    }
}

// ---------------------------------------------------------------------------
// fp16 2-MMA GEMM: C = (Ah + Al) @ W16^T + bias. CTA 128x128, KC=64, 8 warps.
// 3 smem tiles/stage (Ah, Al, B), double-buffered: 108KB -> 2 CTAs/SM.
// MODE 0: fused QKV, split-bf16 outputs. MODE 1: O-proj, fp32 output.
// ---------------------------------------------------------------------------
#define KC 64
#define GPITCH 144                      // 128B data + 16 pad (9-bank stride: conflict-free)
#define GTILE (128 * GPITCH)            // 18432
#define GSTAGE (3 * GTILE)              // 55296: AH, AL, B
#define GEMM_SMEM (2 * GSTAGE)          // 110592

template<int MODE>
__global__ __launch_bounds__(256, 2) void gemm_mma_kernel(
    const __half* __restrict__ Ahi, const __half* __restrict__ Alo,
    const __half* __restrict__ Bh,
    const float* __restrict__ b0, const float* __restrict__ b1,
    const float* __restrict__ b2,
    __nv_bfloat16* __restrict__ o0h, __nv_bfloat16* __restrict__ o0l,
    __nv_bfloat16* __restrict__ o1h, __nv_bfloat16* __restrict__ o1l,
    __nv_bfloat16* __restrict__ o2h, __nv_bfloat16* __restrict__ o2l,
    float* __restrict__ Cf)
{
    extern __shared__ __align__(128) char smem[];
    const uint32_t sbase = smem_to_u32(smem);
    const int tid  = threadIdx.x;
    const int wid  = tid >> 5;
    const int lane = tid & 31;
    const int bm = blockIdx.y * 128;
    const int bn = blockIdx.x * 128;    // index into (possibly concatenated) N
    const int wm = (wid >> 2) * 64;
    const int wn = (wid & 3) * 32;

    float acc[4][4][4];
    #pragma unroll
    for (int mt = 0; mt < 4; mt++)
        #pragma unroll
        for (int nt = 0; nt < 4; nt++)
            #pragma unroll
            for (int i = 0; i < 4; i++) acc[mt][nt][i] = 0.f;

    // stage loader: 128 rows x 8 16B-chunks per tensor; 4 passes of 256 thr
    #define G_LOAD(SB, K0) do {                                                  \
        _Pragma("unroll")                                                        \
        for (int _i = 0; _i < 4; _i++) {                                         \
            int _lin = _i * 256 + tid;                                           \
            int _r = _lin >> 3, _c = _lin & 7;                                   \
            uint32_t _off = (uint32_t)_r * GPITCH + _c * 16;                     \
            size_t _ga = (size_t)(bm + _r) * HD + (K0) + _c * 8;                 \
            size_t _gb = (size_t)(bn + _r) * HD + (K0) + _c * 8;                 \
            cp_async16((SB) + 0*GTILE + _off, Ahi + _ga);                        \
            cp_async16((SB) + 1*GTILE + _off, Alo + _ga);                        \
            cp_async16((SB) + 2*GTILE + _off, Bh  + _gb);                        \
        }                                                                        \
        CP_COMMIT();                                                             \
    } while (0)

    G_LOAD(sbase, 0);

    const int r8 = lane & 7;
    const int g  = lane >> 3;
    const uint32_t a_row_add = (uint32_t)(r8 + ((g & 1) ? 8 : 0)) * GPITCH + ((g & 2) ? 16 : 0);
    const uint32_t b_row_add = (uint32_t)(r8 + ((g >= 2) ? 8 : 0)) * GPITCH + ((g & 1) ? 16 : 0);

    for (int t = 0; t < HD / KC; t++) {
        if (t + 1 < HD / KC) {
            G_LOAD(sbase + ((t + 1) & 1) * GSTAGE, (t + 1) * KC);
            CP_WAIT(1);
        } else {
            CP_WAIT(0);
        }
        __syncthreads();

        const uint32_t sb = sbase + (t & 1) * GSTAGE;
        #pragma unroll
        for (int ks = 0; ks < 4; ks++) {
            uint32_t bh[2][4];
            #pragma unroll
            for (int p = 0; p < 2; p++) {
                uint32_t addr = sb + 2*GTILE + (uint32_t)(wn + p * 16) * GPITCH + ks * 32 + b_row_add;
                ldsm_x4(bh[p][0], bh[p][1], bh[p][2], bh[p][3], addr);
            }
            #pragma unroll
            for (int mt = 0; mt < 4; mt++) {
                uint32_t ah[4], al[4];
                uint32_t addr = sb + (uint32_t)(wm + mt * 16) * GPITCH + ks * 32 + a_row_add;
                ldsm_x4(ah[0], ah[1], ah[2], ah[3], addr + 0*GTILE);
                ldsm_x4(al[0], al[1], al[2], al[3], addr + 1*GTILE);
                #pragma unroll
                for (int nt = 0; nt < 4; nt++) {
                    uint32_t bb0 = bh[nt >> 1][(nt & 1) * 2 + 0];
                    uint32_t bb1 = bh[nt >> 1][(nt & 1) * 2 + 1];
                    mma_f16(acc[mt][nt], ah, bb0, bb1);
                    mma_f16(acc[mt][nt], al, bb0, bb1);
                }
            }
        }
        __syncthreads();
    }

    const int er = lane >> 2;
    const int ec = (lane & 3) * 2;

    if (MODE == 0) {
        const int w  = bn >> 11;            // 0=Q,1=K,2=V
        const int ln = (bn & 2047) + wn;
        const float* bias = (w == 0) ? b0 : (w == 1) ? b1 : b2;
        __nv_bfloat16* oh = (w == 0) ? o0h : (w == 1) ? o1h : o2h;
        __nv_bfloat16* ol = (w == 0) ? o0l : (w == 1) ? o1l : o2l;
        #pragma unroll
        for (int mt = 0; mt < 4; mt++) {
            #pragma unroll
            for (int nt = 0; nt < 4; nt++) {
                int row = bm + wm + mt * 16 + er;
                int col = ln + nt * 8 + ec;
                float bb0 = bias[col], bb1 = bias[col + 1];
                uint32_t h, l;
                split_pack(acc[mt][nt][0] + bb0, acc[mt][nt][1] + bb1, h, l);
                *(uint32_t*)&oh[(size_t)row * HD + col] = h;
                *(uint32_t*)&ol[(size_t)row * HD + col] = l;
                split_pack(acc[mt][nt][2] + bb0, acc[mt][nt][3] + bb1, h, l);
                *(uint32_t*)&oh[(size_t)(row + 8) * HD + col] = h;
                *(uint32_t*)&ol[(size_t)(row + 8) * HD + col] = l;
            }
        }
    } else {
        #pragma unroll
        for (int mt = 0; mt < 4; mt++) {
            #pragma unroll
            for (int nt = 0; nt < 4; nt++) {
                int row = bm + wm + mt * 16 + er;
                int col = bn + wn + nt * 8 + ec;
                float bb0 = b0[col], bb1 = b0[col + 1];
                *(float2*)&Cf[(size_t)row * HD + col] =
                    make_float2(acc[mt][nt][0] + bb0, acc[mt][nt][1] + bb1);
                *(float2*)&Cf[(size_t)(row + 8) * HD + col] =
                    make_float2(acc[mt][nt][2] + bb0, acc[mt][nt][3] + bb1);
            }
        }
    }
}

// ---------------------------------------------------------------------------
// Tensor-core flash attention — bf16 3-MMA (unchanged math), 4 warps, 2 CTAs/SM.
// New: base-2 softmax (scale folds log2e), lazy o-correction, fp16 output split.
// ---------------------------------------------------------------------------
#define AVP 272
#define KTB32 (32 * AVP)            // 8704
#define STB32 (4 * KTB32)           // 34816
#define ATTN_SMEM (2 * STB32)       // 69632
#define QSTG_H 0
#define QSTG_L (64 * AVP)

__global__ __launch_bounds__(128, 2) void attn_mma_kernel(
    const __nv_bfloat16* __restrict__ Qhi, const __nv_bfloat16* __restrict__ Qlo,
    const __nv_bfloat16* __restrict__ Khi, const __nv_bfloat16* __restrict__ Klo,
    const __nv_bfloat16* __restrict__ Vhi, const __nv_bfloat16* __restrict__ Vlo,
    const int* __restrict__ mask,
    __half* __restrict__ Ahi, __half* __restrict__ Alo)
{
    extern __shared__ __align__(128) char smem[];
    const uint32_t sbase = smem_to_u32(smem);
    const int tid  = threadIdx.x;
    const int wid  = tid >> 5;
    const int lane = tid & 31;
    const int q0 = blockIdx.x * 64;
    const int h  = blockIdx.y;
    const int b  = blockIdx.z;
    const int hc = h * DH;

    const int r8 = lane & 7;
    const int g  = lane >> 3;
    const uint32_t a_add = (uint32_t)(r8 + ((g & 1) ? 8 : 0)) * AVP + ((g & 2) ? 16 : 0);
    const uint32_t b_add = (uint32_t)(r8 + ((g >= 2) ? 8 : 0)) * AVP + ((g & 1) ? 16 : 0);
    const uint32_t v_add = (uint32_t)(r8 + ((g & 1) ? 8 : 0)) * AVP + ((g >> 1) ? 16 : 0);

    {
        #pragma unroll
        for (int i = 0; i < 8; i++) {
            int lin = i * 128 + tid;
            int r = lin >> 4, c = lin & 15;
            size_t gq = (size_t)(b * SQ + q0 + r) * HD + hc + c * 8;
            cp_async16(sbase + QSTG_H + (uint32_t)r * AVP + c * 16, Qhi + gq);
            cp_async16(sbase + QSTG_L + (uint32_t)r * AVP + c * 16, Qlo + gq);
        }
        CP_COMMIT();
        CP_WAIT(0);
        __syncthreads();
    }

    uint32_t qh[8][4], ql[8][4];
    #pragma unroll
    for (int ks = 0; ks < 8; ks++) {
        uint32_t addr = (uint32_t)(16 * wid) * AVP + ks * 32 + a_add;
        ldsm_x4(qh[ks][0], qh[ks][1], qh[ks][2], qh[ks][3], sbase + QSTG_H + addr);
        ldsm_x4(ql[ks][0], ql[ks][1], ql[ks][2], ql[ks][3], sbase + QSTG_L + addr);
    }
    __syncthreads();

    #define LOAD_CHUNK32(T, STAGE) do {                                          \
        const uint32_t _sb = sbase + (STAGE) * STB32;                            \
        _Pragma("unroll")                                                        \
        for (int _i = 0; _i < 4; _i++) {                                         \
            int _lin = _i * 128 + tid;                                           \
            int _r = _lin >> 4, _c = _lin & 15;                                  \
            size_t _gk = (size_t)(b * SQ + (T) * 32 + _r) * HD + hc + _c * 8;    \
            uint32_t _off = (uint32_t)_r * AVP + _c * 16;                        \
            cp_async16(_sb + 0*KTB32 + _off, Khi + _gk);                         \
            cp_async16(_sb + 1*KTB32 + _off, Klo + _gk);                         \
            cp_async16(_sb + 2*KTB32 + _off, Vhi + _gk);                         \
            cp_async16(_sb + 3*KTB32 + _off, Vlo + _gk);                         \
        }                                                                        \
        CP_COMMIT();                                                             \
    } while (0)

    LOAD_CHUNK32(0, 0);

    float m0 = -1e30f, m1 = -1e30f, l0 = 0.f, l1 = 0.f;
    float o[16][4];
    #pragma unroll
    for (int nt = 0; nt < 16; nt++)
        #pragma unroll
        for (int i = 0; i < 4; i++) o[nt][i] = 0.f;

    // base-2 softmax: fold log2(e) into the scale
    const float scale2 = 0.08838834764831845f * 1.4426950408889634f;
    const int row0 = q0 + 16 * wid + (lane >> 2);
    const int c2 = (lane & 3) * 2;
    const int* mrow0 = mask + ((size_t)b * SQ + row0) * SQ;
    const int* mrow1 = mrow0 + 8 * SQ;

    for (int t = 0; t < SQ / 32; t++) {
        if (t + 1 < SQ / 32) { LOAD_CHUNK32(t + 1, (t + 1) & 1); CP_WAIT(1); }
        else CP_WAIT(0);
        __syncthreads();

        const uint32_t sb = sbase + (t & 1) * STB32;

        float s[4][4];
        #pragma unroll
        for (int j = 0; j < 4; j++)
            #pragma unroll
            for (int i = 0; i < 4; i++) s[j][i] = 0.f;

        #pragma unroll
        for (int ks = 0; ks < 8; ks++) {
            #pragma unroll
            for (int p = 0; p < 2; p++) {
                uint32_t kh[4], kl[4];
                uint32_t addr = sb + (uint32_t)(16 * p) * AVP + ks * 32 + b_add;
                ldsm_x4(kh[0], kh[1], kh[2], kh[3], addr + 0*KTB32);
                ldsm_x4(kl[0], kl[1], kl[2], kl[3], addr + 1*KTB32);
                mma_bf16(s[2*p],   qh[ks], kh[0], kh[1]);
                mma_bf16(s[2*p],   qh[ks], kl[0], kl[1]);
                mma_bf16(s[2*p],   ql[ks], kh[0], kh[1]);
                mma_bf16(s[2*p+1], qh[ks], kh[2], kh[3]);
                mma_bf16(s[2*p+1], qh[ks], kl[2], kl[3]);
                mma_bf16(s[2*p+1], ql[ks], kh[2], kh[3]);
            }
        }

        const int k0 = t * 32;
        float mx0 = -1e30f, mx1 = -1e30f;
        #pragma unroll
        for (int j = 0; j < 4; j++) {
            int2 mm0 = *(const int2*)&mrow0[k0 + 8*j + c2];
            int2 mm1 = *(const int2*)&mrow1[k0 + 8*j + c2];
            s[j][0] = mm0.x ? s[j][0] * scale2 : -1e30f;
            s[j][1] = mm0.y ? s[j][1] * scale2 : -1e30f;
            s[j][2] = mm1.x ? s[j][2] * scale2 : -1e30f;
            s[j][3] = mm1.y ? s[j][3] * scale2 : -1e30f;
            mx0 = fmaxf(mx0, fmaxf(s[j][0], s[j][1]));
            mx1 = fmaxf(mx1, fmaxf(s[j][2], s[j][3]));
        }
        mx0 = fmaxf(mx0, __shfl_xor_sync(0xffffffffu, mx0, 1));
        mx0 = fmaxf(mx0, __shfl_xor_sync(0xffffffffu, mx0, 2));
        mx1 = fmaxf(mx1, __shfl_xor_sync(0xffffffffu, mx1, 1));
        mx1 = fmaxf(mx1, __shfl_xor_sync(0xffffffffu, mx1, 2));

        float mn0 = fmaxf(m0, mx0), mn1 = fmaxf(m1, mx1);
        float corr0 = ex2(m0 - mn0), corr1 = ex2(m1 - mn1);
        bool upd = (mn0 != m0) || (mn1 != m1);
        m0 = mn0; m1 = mn1;

        float ps0 = 0.f, ps1 = 0.f;
        #pragma unroll
        for (int j = 0; j < 4; j++) {
            s[j][0] = ex2(s[j][0] - m0);
            s[j][1] = ex2(s[j][1] - m0);
            s[j][2] = ex2(s[j][2] - m1);
            s[j][3] = ex2(s[j][3] - m1);
            ps0 += s[j][0] + s[j][1];
            ps1 += s[j][2] + s[j][3];
        }
        ps0 += __shfl_xor_sync(0xffffffffu, ps0, 1);
        ps0 += __shfl_xor_sync(0xffffffffu, ps0, 2);
        ps1 += __shfl_xor_sync(0xffffffffu, ps1, 1);
        ps1 += __shfl_xor_sync(0xffffffffu, ps1, 2);
        l0 = l0 * corr0 + ps0;
        l1 = l1 * corr1 + ps1;

        // lazy o-rescale: skip when no row max in the warp changed
        if (__any_sync(0xffffffffu, upd)) {
            #pragma unroll
            for (int nt = 0; nt < 16; nt++) {
                o[nt][0] *= corr0; o[nt][1] *= corr0;
                o[nt][2] *= corr1; o[nt][3] *= corr1;
            }
        }

        #pragma unroll
        for (int ks2 = 0; ks2 < 2; ks2++) {
            uint32_t ph[4], pl[4];
            split_pack(s[2*ks2][0],   s[2*ks2][1],   ph[0], pl[0]);
            split_pack(s[2*ks2][2],   s[2*ks2][3],   ph[1], pl[1]);
            split_pack(s[2*ks2+1][0], s[2*ks2+1][1], ph[2], pl[2]);
            split_pack(s[2*ks2+1][2], s[2*ks2+1][3], ph[3], pl[3]);
            #pragma unroll
            for (int dp = 0; dp < 8; dp++) {
                uint32_t vh[4], vl[4];
                uint32_t addr = sb + (uint32_t)(16 * ks2) * AVP + dp * 32 + v_add;
                ldsm_x4_t(vh[0], vh[1], vh[2], vh[3], addr + 2*KTB32);
                ldsm_x4_t(vl[0], vl[1], vl[2], vl[3], addr + 3*KTB32);
                mma_bf16(o[2*dp],   ph, vh[0], vh[1]);
                mma_bf16(o[2*dp],   ph, vl[0], vl[1]);
                mma_bf16(o[2*dp],   pl, vh[0], vh[1]);
                mma_bf16(o[2*dp+1], ph, vh[2], vh[3]);
                mma_bf16(o[2*dp+1], ph, vl[2], vl[3]);
                mma_bf16(o[2*dp+1], pl, vh[2], vh[3]);
            }
        }
        __syncthreads();
    }

    // ---- epilogue: normalize, fp16 split for the O-projection ----
    const float inv0 = 1.f / l0, inv1 = 1.f / l1;
    const size_t ob0 = (size_t)(b * SQ + row0) * HD + hc;
    const size_t ob1 = ob0 + (size_t)8 * HD;
    #pragma unroll
    for (int nt = 0; nt < 16; nt++) {
        int col = 8 * nt + c2;
        uint32_t hh, ll;
        split_pack_h(o[nt][0] * inv0, o[nt][1] * inv0, hh, ll);
        *(uint32_t*)&Ahi[ob0 + col] = hh;
        *(uint32_t*)&Alo[ob0 + col] = ll;
        split_pack_h(o[nt][2] * inv1, o[nt][3] * inv1, hh, ll);
        *(uint32_t*)&Ahi[ob1 + col] = hh;
        *(uint32_t*)&Alo[ob1 + col] = ll;
    }
}

// ---------------------------------------------------------------------------

extern "C" void kernel_launch(void* const* d_in, const int* in_sizes, int n_in,
                              void* d_out, int out_size)
{
    const float* X   = (const float*)d_in[0];
    const int*   msk = (const int*)  d_in[1];
    const float* Wq  = (const float*)d_in[2];
    const float* bq  = (const float*)d_in[3];
    const float* Wk  = (const float*)d_in[4];
    const float* bk  = (const float*)d_in[5];
    const float* Wv  = (const float*)d_in[6];
    const float* bv  = (const float*)d_in[7];
    const float* Wo  = (const float*)d_in[8];
    const float* bo  = (const float*)d_in[9];
    float* out = (float*)d_out;

    __nv_bfloat16 *Qhi, *Qlo, *Khi, *Klo, *Vhi, *Vlo;
    __half *Ahi, *Alo, *Xhi, *Xlo, *Wt;
    cudaGetSymbolAddress((void**)&Qhi, g_Qhi);
    cudaGetSymbolAddress((void**)&Qlo, g_Qlo);
    cudaGetSymbolAddress((void**)&Khi, g_Khi);
    cudaGetSymbolAddress((void**)&Klo, g_Klo);
    cudaGetSymbolAddress((void**)&Vhi, g_Vhi);
    cudaGetSymbolAddress((void**)&Vlo, g_Vlo);
    cudaGetSymbolAddress((void**)&Ahi, g_Ahi);
    cudaGetSymbolAddress((void**)&Alo, g_Alo);
    cudaGetSymbolAddress((void**)&Xhi, g_Xhi);
    cudaGetSymbolAddress((void**)&Xlo, g_Xlo);
    cudaGetSymbolAddress((void**)&Wt,  g_Wt);

    const size_t WSZ = (size_t)HD * HD;
    const int n4 = MR * HD / 4;

    cudaFuncSetAttribute(gemm_mma_kernel<0>,
                         cudaFuncAttributeMaxDynamicSharedMemorySize, GEMM_SMEM);
    cudaFuncSetAttribute(gemm_mma_kernel<1>,
                         cudaFuncAttributeMaxDynamicSharedMemorySize, GEMM_SMEM);
    cudaFuncSetAttribute(attn_mma_kernel,
                         cudaFuncAttributeMaxDynamicSharedMemorySize, ATTN_SMEM);

    // 1. fp16 hi/lo split of X; batched weight transpose -> single fp16
    cvt_split_h_kernel<<<n4 / 256, 256>>>((const float4*)X, Xhi, Xlo, n4);
    dim3 wg(HD / 32, HD / 32, 4), wb(32, 8);
    cvt_wt_kernel<<<wg, wb>>>(Wq, Wk, Wv, Wo, Wt);

    // 2. Fused Q/K/V projection (fp16 2-MMA) -> bf16 split outputs for attention
    dim3 gq(3 * HD / 128, MR / 128);   // (48, 32)
    gemm_mma_kernel<0><<<gq, 256, GEMM_SMEM>>>(
        Xhi, Xlo, Wt, bq, bk, bv,
        Qhi, Qlo, Khi, Klo, Vhi, Vlo, nullptr);

    // 3. tensor-core flash attention (bf16 3-MMA) -> fp16 split A
    dim3 ga(SQ / 64, NH, BB);          // (32, 16, 2)
    attn_mma_kernel<<<ga, 128, ATTN_SMEM>>>(Qhi, Qlo, Khi, Klo, Vhi, Vlo, msk, Ahi, Alo);

    // 4. output projection (fp16 2-MMA) -> fp32 out
    dim3 go(HD / 128, MR / 128);       // (16, 32)
    gemm_mma_kernel<1><<<go, 256, GEMM_SMEM>>>(
        Ahi, Alo, Wt + 3*WSZ, bo, bo, bo,
        nullptr, nullptr, nullptr, nullptr, nullptr, nullptr, out);
}

// round 11
// speedup vs baseline: 1.6191x; 1.2078x over previous
#include <cuda_runtime.h>
#include <cuda_bf16.h>
#include <cuda_fp16.h>
#include <cstdint>

#define HD 2048
#define NH 16
#define DH 128
#define BB 2
#define SQ 2048
#define MR (BB*SQ)   // 4096 rows

// ---------------------------------------------------------------------------
// Scratch (device globals; no allocations allowed)
// ---------------------------------------------------------------------------
__device__ __half g_Qh[(size_t)MR*HD];
__device__ __half g_Ql[(size_t)MR*HD];
__device__ __half g_K16[(size_t)MR*HD];
__device__ __half g_V16[(size_t)MR*HD];
__device__ __half g_Ahi[(size_t)MR*HD];
__device__ __half g_Alo[(size_t)MR*HD];
__device__ __half g_Xhi[(size_t)MR*HD];
__device__ __half g_Xlo[(size_t)MR*HD];
__device__ __half g_Wt[4][(size_t)HD*HD];    // transposed [n][k], single fp16; Q,K,V contiguous

// ---------------------------------------------------------------------------
// PTX helpers (compute_103-safe)
// ---------------------------------------------------------------------------
__device__ __forceinline__ uint32_t smem_to_u32(const void* p) {
    uint32_t a;
    asm("{ .reg .u64 t; cvta.to.shared.u64 t, %1; cvt.u32.u64 %0, t; }"
        : "=r"(a) : "l"(p));
    return a;
}
__device__ __forceinline__ void cp_async16(uint32_t s, const void* g) {
    asm volatile("cp.async.cg.shared.global [%0], [%1], 16;" :: "r"(s), "l"(g));
}
#define CP_COMMIT() asm volatile("cp.async.commit_group;" ::: "memory")
#define CP_WAIT(n)  asm volatile("cp.async.wait_group %0;" :: "n"(n) : "memory")

__device__ __forceinline__ void ldsm_x4(uint32_t& r0, uint32_t& r1,
                                        uint32_t& r2, uint32_t& r3, uint32_t addr) {
    asm volatile("ldmatrix.sync.aligned.m8n8.x4.shared.b16 {%0,%1,%2,%3}, [%4];"
        : "=r"(r0), "=r"(r1), "=r"(r2), "=r"(r3) : "r"(addr));
}
__device__ __forceinline__ void ldsm_x4_t(uint32_t& r0, uint32_t& r1,
                                          uint32_t& r2, uint32_t& r3, uint32_t addr) {
    asm volatile("ldmatrix.sync.aligned.m8n8.x4.trans.shared.b16 {%0,%1,%2,%3}, [%4];"
        : "=r"(r0), "=r"(r1), "=r"(r2), "=r"(r3) : "r"(addr));
}
__device__ __forceinline__ void mma_f16(float* c, const uint32_t* a,
                                        uint32_t b0, uint32_t b1) {
    asm volatile(
        "mma.sync.aligned.m16n8k16.row.col.f32.f16.f16.f32 "
        "{%0,%1,%2,%3}, {%4,%5,%6,%7}, {%8,%9}, {%0,%1,%2,%3};"
        : "+f"(c[0]), "+f"(c[1]), "+f"(c[2]), "+f"(c[3])
        : "r"(a[0]), "r"(a[1]), "r"(a[2]), "r"(a[3]), "r"(b0), "r"(b1));
}
__device__ __forceinline__ float ex2(float x) {
    float y;
    asm("ex2.approx.ftz.f32 %0, %1;" : "=f"(y) : "f"(x));
    return y;
}
// fp32 pair -> fp16 hi + fp16 residual
__device__ __forceinline__ void split_pack_h(float x, float y, uint32_t& hi, uint32_t& lo) {
    __half hx = __float2half_rn(x);
    __half hy = __float2half_rn(y);
    __half lx = __float2half_rn(x - __half2float(hx));
    __half ly = __float2half_rn(y - __half2float(hy));
    __half2 h(hx, hy), l(lx, ly);
    hi = *(uint32_t*)&h;
    lo = *(uint32_t*)&l;
}
__device__ __forceinline__ uint32_t pack_h2(float x, float y) {
    __half2 h(__float2half_rn(x), __float2half_rn(y));
    return *(uint32_t*)&h;
}

// ---------------------------------------------------------------------------
// Conversion kernels
// ---------------------------------------------------------------------------
__global__ __launch_bounds__(256) void cvt_split_h_kernel(
    const float4* __restrict__ in, __half* __restrict__ hi,
    __half* __restrict__ lo, int n4)
{
    int i = blockIdx.x * 256 + threadIdx.x;
    if (i >= n4) return;
    float4 v = in[i];
    float f[4] = {v.x, v.y, v.z, v.w};
    #pragma unroll
    for (int p = 0; p < 2; p++) {
        uint32_t h, l;
        split_pack_h(f[2*p+0], f[2*p+1], h, l);
        ((uint32_t*)hi)[2*i+p] = h;
        ((uint32_t*)lo)[2*i+p] = l;
    }
}

// Batched: W[K,N] fp32 -> Wt[n][k] single fp16. blockIdx.z selects weight.
__global__ __launch_bounds__(256) void cvt_wt_kernel(
    const float* __restrict__ W0, const float* __restrict__ W1,
    const float* __restrict__ W2, const float* __restrict__ W3,
    __half* __restrict__ outb)
{
    __shared__ float tile[32][33];
    const int z = blockIdx.z;
    const float* W = (z == 0) ? W0 : (z == 1) ? W1 : (z == 2) ? W2 : W3;
    __half* o = outb + (size_t)z * HD * HD;
    const int n0 = blockIdx.x * 32, k0 = blockIdx.y * 32;
    const int tx = threadIdx.x, ty = threadIdx.y;
    #pragma unroll
    for (int i = 0; i < 4; i++)
        tile[ty + 8*i][tx] = W[(size_t)(k0 + ty + 8*i) * HD + n0 + tx];
    __syncthreads();
    #pragma unroll
    for (int i = 0; i < 4; i++) {
        float v = tile[tx][ty + 8*i];
        o[(size_t)(n0 + ty + 8*i) * HD + k0 + tx] = __float2half_rn(v);
    }
}

// ---------------------------------------------------------------------------
// fp16 2-MMA GEMM: C = (Ah + Al) @ W16^T + bias. CTA 128x128, KC=64, 8 warps.
// MODE 0: fused QKV — Q out as fp16 hi/lo, K and V out as single fp16.
// MODE 1: O-proj — fp32 output + bias.
// ---------------------------------------------------------------------------
#define KC 64
#define GPITCH 144
#define GTILE (128 * GPITCH)            // 18432
#define GSTAGE (3 * GTILE)              // 55296: AH, AL, B
#define GEMM_SMEM (2 * GSTAGE)          // 110592

template<int MODE>
__global__ __launch_bounds__(256, 2) void gemm_mma_kernel(
    const __half* __restrict__ Ahi, const __half* __restrict__ Alo,
    const __half* __restrict__ Bh,
    const float* __restrict__ b0, const float* __restrict__ b1,
    const float* __restrict__ b2,
    __half* __restrict__ oQh, __half* __restrict__ oQl,
    __half* __restrict__ oK, __half* __restrict__ oV,
    float* __restrict__ Cf)
{
    extern __shared__ __align__(128) char smem[];
    const uint32_t sbase = smem_to_u32(smem);
    const int tid  = threadIdx.x;
    const int wid  = tid >> 5;
    const int lane = tid & 31;
    const int bm = blockIdx.y * 128;
    const int bn = blockIdx.x * 128;
    const int wm = (wid >> 2) * 64;
    const int wn = (wid & 3) * 32;

    float acc[4][4][4];
    #pragma unroll
    for (int mt = 0; mt < 4; mt++)
        #pragma unroll
        for (int nt = 0; nt < 4; nt++)
            #pragma unroll
            for (int i = 0; i < 4; i++) acc[mt][nt][i] = 0.f;

    #define G_LOAD(SB, K0) do {                                                  \
        _Pragma("unroll")                                                        \
        for (int _i = 0; _i < 4; _i++) {                                         \
            int _lin = _i * 256 + tid;                                           \
            int _r = _lin >> 3, _c = _lin & 7;                                   \
            uint32_t _off = (uint32_t)_r * GPITCH + _c * 16;                     \
            size_t _ga = (size_t)(bm + _r) * HD + (K0) + _c * 8;                 \
            size_t _gb = (size_t)(bn + _r) * HD + (K0) + _c * 8;                 \
            cp_async16((SB) + 0*GTILE + _off, Ahi + _ga);                        \
            cp_async16((SB) + 1*GTILE + _off, Alo + _ga);                        \
            cp_async16((SB) + 2*GTILE + _off, Bh  + _gb);                        \
        }                                                                        \
        CP_COMMIT();                                                             \
    } while (0)

    G_LOAD(sbase, 0);

    const int r8 = lane & 7;
    const int g  = lane >> 3;
    const uint32_t a_row_add = (uint32_t)(r8 + ((g & 1) ? 8 : 0)) * GPITCH + ((g & 2) ? 16 : 0);
    const uint32_t b_row_add = (uint32_t)(r8 + ((g >= 2) ? 8 : 0)) * GPITCH + ((g & 1) ? 16 : 0);

    for (int t = 0; t < HD / KC; t++) {
        if (t + 1 < HD / KC) {
            G_LOAD(sbase + ((t + 1) & 1) * GSTAGE, (t + 1) * KC);
            CP_WAIT(1);
        } else {
            CP_WAIT(0);
        }
        __syncthreads();

        const uint32_t sb = sbase + (t & 1) * GSTAGE;
        #pragma unroll
        for (int ks = 0; ks < 4; ks++) {
            uint32_t bh[2][4];
            #pragma unroll
            for (int p = 0; p < 2; p++) {
                uint32_t addr = sb + 2*GTILE + (uint32_t)(wn + p * 16) * GPITCH + ks * 32 + b_row_add;
                ldsm_x4(bh[p][0], bh[p][1], bh[p][2], bh[p][3], addr);
            }
            #pragma unroll
            for (int mt = 0; mt < 4; mt++) {
                uint32_t ah[4], al[4];
                uint32_t addr = sb + (uint32_t)(wm + mt * 16) * GPITCH + ks * 32 + a_row_add;
                ldsm_x4(ah[0], ah[1], ah[2], ah[3], addr + 0*GTILE);
                ldsm_x4(al[0], al[1], al[2], al[3], addr + 1*GTILE);
                #pragma unroll
                for (int nt = 0; nt < 4; nt++) {
                    uint32_t bb0 = bh[nt >> 1][(nt & 1) * 2 + 0];
                    uint32_t bb1 = bh[nt >> 1][(nt & 1) * 2 + 1];
                    mma_f16(acc[mt][nt], ah, bb0, bb1);
                    mma_f16(acc[mt][nt], al, bb0, bb1);
                }
            }
        }
        __syncthreads();
    }

    const int er = lane >> 2;
    const int ec = (lane & 3) * 2;

    if (MODE == 0) {
        const int w  = bn >> 11;            // 0=Q,1=K,2=V
        const int ln = (bn & 2047) + wn;
        const float* bias = (w == 0) ? b0 : (w == 1) ? b1 : b2;
        #pragma unroll
        for (int mt = 0; mt < 4; mt++) {
            #pragma unroll
            for (int nt = 0; nt < 4; nt++) {
                int row = bm + wm + mt * 16 + er;
                int col = ln + nt * 8 + ec;
                float bb0 = bias[col], bb1 = bias[col + 1];
                float v0 = acc[mt][nt][0] + bb0, v1 = acc[mt][nt][1] + bb1;
                float v2 = acc[mt][nt][2] + bb0, v3 = acc[mt][nt][3] + bb1;
                if (w == 0) {
                    uint32_t h, l;
                    split_pack_h(v0, v1, h, l);
                    *(uint32_t*)&oQh[(size_t)row * HD + col] = h;
                    *(uint32_t*)&oQl[(size_t)row * HD + col] = l;
                    split_pack_h(v2, v3, h, l);
                    *(uint32_t*)&oQh[(size_t)(row + 8) * HD + col] = h;
                    *(uint32_t*)&oQl[(size_t)(row + 8) * HD + col] = l;
                } else {
                    __half* dst = (w == 1) ? oK : oV;
                    *(uint32_t*)&dst[(size_t)row * HD + col] = pack_h2(v0, v1);
                    *(uint32_t*)&dst[(size_t)(row + 8) * HD + col] = pack_h2(v2, v3);
                }
            }
        }
    } else {
        #pragma unroll
        for (int mt = 0; mt < 4; mt++) {
            #pragma unroll
            for (int nt = 0; nt < 4; nt++) {
                int row = bm + wm + mt * 16 + er;
                int col = bn + wn + nt * 8 + ec;
                float bb0 = b0[col], bb1 = b0[col + 1];
                *(float2*)&Cf[(size_t)row * HD + col] =
                    make_float2(acc[mt][nt][0] + bb0, acc[mt][nt][1] + bb1);
                *(float2*)&Cf[(size_t)(row + 8) * HD + col] =
                    make_float2(acc[mt][nt][2] + bb0, acc[mt][nt][3] + bb1);
            }
        }
    }
}

// ---------------------------------------------------------------------------
// Tensor-core flash attention, fp16 2-MMA on both phases.
// S = (Qh+Ql)·K16 ; O += (Ph+Pl)·V16. 4 warps, 2 CTAs/SM, K/V double-buffered.
// ---------------------------------------------------------------------------
#define AVP 272
#define KTB32 (32 * AVP)            // 8704 per tile (32 rows x 128 fp16)
#define STB32 (2 * KTB32)           // 17408 per stage (K16, V16)
#define ATTN_SMEM (2 * STB32)       // 34816
#define QSTG_H 0
#define QSTG_L (64 * AVP)           // 17408 (Q staging overlays the K/V stages)

__global__ __launch_bounds__(128, 2) void attn_mma_kernel(
    const __half* __restrict__ Qh16, const __half* __restrict__ Ql16,
    const __half* __restrict__ K16, const __half* __restrict__ V16,
    const int* __restrict__ mask,
    __half* __restrict__ Ahi, __half* __restrict__ Alo)
{
    extern __shared__ __align__(128) char smem[];
    const uint32_t sbase = smem_to_u32(smem);
    const int tid  = threadIdx.x;
    const int wid  = tid >> 5;
    const int lane = tid & 31;
    const int q0 = blockIdx.x * 64;
    const int h  = blockIdx.y;
    const int b  = blockIdx.z;
    const int hc = h * DH;

    const int r8 = lane & 7;
    const int g  = lane >> 3;
    const uint32_t a_add = (uint32_t)(r8 + ((g & 1) ? 8 : 0)) * AVP + ((g & 2) ? 16 : 0);
    const uint32_t b_add = (uint32_t)(r8 + ((g >= 2) ? 8 : 0)) * AVP + ((g & 1) ? 16 : 0);
    const uint32_t v_add = (uint32_t)(r8 + ((g & 1) ? 8 : 0)) * AVP + ((g >> 1) ? 16 : 0);

    // ---- stage Q (64 x 128, hi+lo) and pull into registers ----
    {
        #pragma unroll
        for (int i = 0; i < 8; i++) {
            int lin = i * 128 + tid;       // 1024 16B-chunks per tensor
            int r = lin >> 4, c = lin & 15;
            size_t gq = (size_t)(b * SQ + q0 + r) * HD + hc + c * 8;
            cp_async16(sbase + QSTG_H + (uint32_t)r * AVP + c * 16, Qh16 + gq);
            cp_async16(sbase + QSTG_L + (uint32_t)r * AVP + c * 16, Ql16 + gq);
        }
        CP_COMMIT();
        CP_WAIT(0);
        __syncthreads();
    }

    uint32_t qh[8][4], ql[8][4];
    #pragma unroll
    for (int ks = 0; ks < 8; ks++) {
        uint32_t addr = (uint32_t)(16 * wid) * AVP + ks * 32 + a_add;
        ldsm_x4(qh[ks][0], qh[ks][1], qh[ks][2], qh[ks][3], sbase + QSTG_H + addr);
        ldsm_x4(ql[ks][0], ql[ks][1], ql[ks][2], ql[ks][3], sbase + QSTG_L + addr);
    }
    __syncthreads();   // Q staging space becomes K/V stages

    #define LOAD_CHUNK32(T, STAGE) do {                                          \
        const uint32_t _sb = sbase + (STAGE) * STB32;                            \
        _Pragma("unroll")                                                        \
        for (int _i = 0; _i < 4; _i++) {                                         \
            int _lin = _i * 128 + tid;        /* 512 16B-chunks per tensor */    \
            int _r = _lin >> 4, _c = _lin & 15;                                  \
            size_t _gk = (size_t)(b * SQ + (T) * 32 + _r) * HD + hc + _c * 8;    \
            uint32_t _off = (uint32_t)_r * AVP + _c * 16;                        \
            cp_async16(_sb + 0*KTB32 + _off, K16 + _gk);                         \
            cp_async16(_sb + 1*KTB32 + _off, V16 + _gk);                         \
        }                                                                        \
        CP_COMMIT();                                                             \
    } while (0)

    LOAD_CHUNK32(0, 0);

    float m0 = -1e30f, m1 = -1e30f, l0 = 0.f, l1 = 0.f;
    float o[16][4];
    #pragma unroll
    for (int nt = 0; nt < 16; nt++)
        #pragma unroll
        for (int i = 0; i < 4; i++) o[nt][i] = 0.f;

    const float scale2 = 0.08838834764831845f * 1.4426950408889634f;
    const int row0 = q0 + 16 * wid + (lane >> 2);
    const int c2 = (lane & 3) * 2;
    const int* mrow0 = mask + ((size_t)b * SQ + row0) * SQ;
    const int* mrow1 = mrow0 + 8 * SQ;

    for (int t = 0; t < SQ / 32; t++) {
        if (t + 1 < SQ / 32) { LOAD_CHUNK32(t + 1, (t + 1) & 1); CP_WAIT(1); }
        else CP_WAIT(0);
        __syncthreads();

        const uint32_t sb = sbase + (t & 1) * STB32;

        // ---- S = (Qh+Ql) K16^T over 32 keys (2 MMAs per step) ----
        float s[4][4];
        #pragma unroll
        for (int j = 0; j < 4; j++)
            #pragma unroll
            for (int i = 0; i < 4; i++) s[j][i] = 0.f;

        #pragma unroll
        for (int ks = 0; ks < 8; ks++) {
            #pragma unroll
            for (int p = 0; p < 2; p++) {
                uint32_t kh[4];
                uint32_t addr = sb + (uint32_t)(16 * p) * AVP + ks * 32 + b_add;
                ldsm_x4(kh[0], kh[1], kh[2], kh[3], addr);
                mma_f16(s[2*p],   qh[ks], kh[0], kh[1]);
                mma_f16(s[2*p],   ql[ks], kh[0], kh[1]);
                mma_f16(s[2*p+1], qh[ks], kh[2], kh[3]);
                mma_f16(s[2*p+1], ql[ks], kh[2], kh[3]);
            }
        }

        // ---- mask + scale + online softmax (base-2, warp-private) ----
        const int k0 = t * 32;
        float mx0 = -1e30f, mx1 = -1e30f;
        #pragma unroll
        for (int j = 0; j < 4; j++) {
            int2 mm0 = *(const int2*)&mrow0[k0 + 8*j + c2];
            int2 mm1 = *(const int2*)&mrow1[k0 + 8*j + c2];
            s[j][0] = mm0.x ? s[j][0] * scale2 : -1e30f;
            s[j][1] = mm0.y ? s[j][1] * scale2 : -1e30f;
            s[j][2] = mm1.x ? s[j][2] * scale2 : -1e30f;
            s[j][3] = mm1.y ? s[j][3] * scale2 : -1e30f;
            mx0 = fmaxf(mx0, fmaxf(s[j][0], s[j][1]));
            mx1 = fmaxf(mx1, fmaxf(s[j][2], s[j][3]));
        }
        mx0 = fmaxf(mx0, __shfl_xor_sync(0xffffffffu, mx0, 1));
        mx0 = fmaxf(mx0, __shfl_xor_sync(0xffffffffu, mx0, 2));
        mx1 = fmaxf(mx1, __shfl_xor_sync(0xffffffffu, mx1, 1));
        mx1 = fmaxf(mx1, __shfl_xor_sync(0xffffffffu, mx1, 2));

        float mn0 = fmaxf(m0, mx0), mn1 = fmaxf(m1, mx1);
        float corr0 = ex2(m0 - mn0), corr1 = ex2(m1 - mn1);
        bool upd = (mn0 != m0) || (mn1 != m1);
        m0 = mn0; m1 = mn1;

        float ps0 = 0.f, ps1 = 0.f;
        #pragma unroll
        for (int j = 0; j < 4; j++) {
            s[j][0] = ex2(s[j][0] - m0);
            s[j][1] = ex2(s[j][1] - m0);
            s[j][2] = ex2(s[j][2] - m1);
            s[j][3] = ex2(s[j][3] - m1);
            ps0 += s[j][0] + s[j][1];
            ps1 += s[j][2] + s[j][3];
        }
        ps0 += __shfl_xor_sync(0xffffffffu, ps0, 1);
        ps0 += __shfl_xor_sync(0xffffffffu, ps0, 2);
        ps1 += __shfl_xor_sync(0xffffffffu, ps1, 1);
        ps1 += __shfl_xor_sync(0xffffffffu, ps1, 2);
        l0 = l0 * corr0 + ps0;
        l1 = l1 * corr1 + ps1;

        if (__any_sync(0xffffffffu, upd)) {
            #pragma unroll
            for (int nt = 0; nt < 16; nt++) {
                o[nt][0] *= corr0; o[nt][1] *= corr0;
                o[nt][2] *= corr1; o[nt][3] *= corr1;
            }
        }

        // ---- O += (Ph+Pl) V16 (2 MMAs per step) ----
        #pragma unroll
        for (int ks2 = 0; ks2 < 2; ks2++) {
            uint32_t ph[4], pl[4];
            split_pack_h(s[2*ks2][0],   s[2*ks2][1],   ph[0], pl[0]);
            split_pack_h(s[2*ks2][2],   s[2*ks2][3],   ph[1], pl[1]);
            split_pack_h(s[2*ks2+1][0], s[2*ks2+1][1], ph[2], pl[2]);
            split_pack_h(s[2*ks2+1][2], s[2*ks2+1][3], ph[3], pl[3]);
            #pragma unroll
            for (int dp = 0; dp < 8; dp++) {
                uint32_t vh[4];
                uint32_t addr = sb + 1*KTB32 + (uint32_t)(16 * ks2) * AVP + dp * 32 + v_add;
                ldsm_x4_t(vh[0], vh[1], vh[2], vh[3], addr);
                mma_f16(o[2*dp],   ph, vh[0], vh[1]);
                mma_f16(o[2*dp],   pl, vh[0], vh[1]);
                mma_f16(o[2*dp+1], ph, vh[2], vh[3]);
                mma_f16(o[2*dp+1], pl, vh[2], vh[3]);
            }
        }
        __syncthreads();
    }

    // ---- epilogue: normalize, fp16 split for the O-projection ----
    const float inv0 = 1.f / l0, inv1 = 1.f / l1;
    const size_t ob0 = (size_t)(b * SQ + row0) * HD + hc;
    const size_t ob1 = ob0 + (size_t)8 * HD;
    #pragma unroll
    for (int nt = 0; nt < 16; nt++) {
        int col = 8 * nt + c2;
        uint32_t hh, ll;
        split_pack_h(o[nt][0] * inv0, o[nt][1] * inv0, hh, ll);
        *(uint32_t*)&Ahi[ob0 + col] = hh;
        *(uint32_t*)&Alo[ob0 + col] = ll;
        split_pack_h(o[nt][2] * inv1, o[nt][3] * inv1, hh, ll);
        *(uint32_t*)&Ahi[ob1 + col] = hh;
        *(uint32_t*)&Alo[ob1 + col] = ll;
    }
}

// ---------------------------------------------------------------------------

extern "C" void kernel_launch(void* const* d_in, const int* in_sizes, int n_in,
                              void* d_out, int out_size)
{
    const float* X   = (const float*)d_in[0];
    const int*   msk = (const int*)  d_in[1];
    const float* Wq  = (const float*)d_in[2];
    const float* bq  = (const float*)d_in[3];
    const float* Wk  = (const float*)d_in[4];
    const float* bk  = (const float*)d_in[5];
    const float* Wv  = (const float*)d_in[6];
    const float* bv  = (const float*)d_in[7];
    const float* Wo  = (const float*)d_in[8];
    const float* bo  = (const float*)d_in[9];
    float* out = (float*)d_out;

    __half *Qh, *Ql, *K16, *V16, *Ahi, *Alo, *Xhi, *Xlo, *Wt;
    cudaGetSymbolAddress((void**)&Qh,  g_Qh);
    cudaGetSymbolAddress((void**)&Ql,  g_Ql);
    cudaGetSymbolAddress((void**)&K16, g_K16);
    cudaGetSymbolAddress((void**)&V16, g_V16);
    cudaGetSymbolAddress((void**)&Ahi, g_Ahi);
    cudaGetSymbolAddress((void**)&Alo, g_Alo);
    cudaGetSymbolAddress((void**)&Xhi, g_Xhi);
    cudaGetSymbolAddress((void**)&Xlo, g_Xlo);
    cudaGetSymbolAddress((void**)&Wt,  g_Wt);

    const size_t WSZ = (size_t)HD * HD;
    const int n4 = MR * HD / 4;

    cudaFuncSetAttribute(gemm_mma_kernel<0>,
                         cudaFuncAttributeMaxDynamicSharedMemorySize, GEMM_SMEM);
    cudaFuncSetAttribute(gemm_mma_kernel<1>,
                         cudaFuncAttributeMaxDynamicSharedMemorySize, GEMM_SMEM);
    cudaFuncSetAttribute(attn_mma_kernel,
                         cudaFuncAttributeMaxDynamicSharedMemorySize, ATTN_SMEM);

    // 1. fp16 hi/lo split of X; batched weight transpose -> single fp16
    cvt_split_h_kernel<<<n4 / 256, 256>>>((const float4*)X, Xhi, Xlo, n4);
    dim3 wg(HD / 32, HD / 32, 4), wb(32, 8);
    cvt_wt_kernel<<<wg, wb>>>(Wq, Wk, Wv, Wo, Wt);

    // 2. Fused Q/K/V projection -> Q fp16 hi/lo, K/V single fp16
    dim3 gq(3 * HD / 128, MR / 128);   // (48, 32)
    gemm_mma_kernel<0><<<gq, 256, GEMM_SMEM>>>(
        Xhi, Xlo, Wt, bq, bk, bv,
        Qh, Ql, K16, V16, nullptr);

    // 3. fp16 2-MMA flash attention -> fp16 split A
    dim3 ga(SQ / 64, NH, BB);          // (32, 16, 2)
    attn_mma_kernel<<<ga, 128, ATTN_SMEM>>>(Qh, Ql, K16, V16, msk, Ahi, Alo);

    // 4. output projection (fp16 2-MMA) -> fp32 out
    dim3 go(HD / 128, MR / 128);       // (16, 32)
    gemm_mma_kernel<1><<<go, 256, GEMM_SMEM>>>(
        Ahi, Alo, Wt + 3*WSZ, bo, bo, bo,
        nullptr, nullptr, nullptr, nullptr, out);
}

// round 12
// speedup vs baseline: 1.6807x; 1.0380x over previous
#include <cuda_runtime.h>
#include <cuda_bf16.h>
#include <cuda_fp16.h>
#include <cstdint>

#define HD 2048
#define NH 16
#define DH 128
#define BB 2
#define SQ 2048
#define MR (BB*SQ)   // 4096 rows

// ---------------------------------------------------------------------------
// Scratch (device globals; no allocations allowed)
// ---------------------------------------------------------------------------
__device__ __half g_Q16[(size_t)MR*HD];
__device__ __half g_K16[(size_t)MR*HD];
__device__ __half g_V16[(size_t)MR*HD];
__device__ __half g_Ahi[(size_t)MR*HD];
__device__ __half g_Alo[(size_t)MR*HD];
__device__ __half g_Xhi[(size_t)MR*HD];
__device__ __half g_Xlo[(size_t)MR*HD];
__device__ __half g_Wt[4][(size_t)HD*HD];    // transposed [n][k], single fp16; Q,K,V contiguous

// ---------------------------------------------------------------------------
// PTX helpers (compute_103-safe)
// ---------------------------------------------------------------------------
__device__ __forceinline__ uint32_t smem_to_u32(const void* p) {
    uint32_t a;
    asm("{ .reg .u64 t; cvta.to.shared.u64 t, %1; cvt.u32.u64 %0, t; }"
        : "=r"(a) : "l"(p));
    return a;
}
__device__ __forceinline__ void cp_async16(uint32_t s, const void* g) {
    asm volatile("cp.async.cg.shared.global [%0], [%1], 16;" :: "r"(s), "l"(g));
}
#define CP_COMMIT() asm volatile("cp.async.commit_group;" ::: "memory")
#define CP_WAIT(n)  asm volatile("cp.async.wait_group %0;" :: "n"(n) : "memory")

__device__ __forceinline__ void ldsm_x4(uint32_t& r0, uint32_t& r1,
                                        uint32_t& r2, uint32_t& r3, uint32_t addr) {
    asm volatile("ldmatrix.sync.aligned.m8n8.x4.shared.b16 {%0,%1,%2,%3}, [%4];"
        : "=r"(r0), "=r"(r1), "=r"(r2), "=r"(r3) : "r"(addr));
}
__device__ __forceinline__ void ldsm_x4_t(uint32_t& r0, uint32_t& r1,
                                          uint32_t& r2, uint32_t& r3, uint32_t addr) {
    asm volatile("ldmatrix.sync.aligned.m8n8.x4.trans.shared.b16 {%0,%1,%2,%3}, [%4];"
        : "=r"(r0), "=r"(r1), "=r"(r2), "=r"(r3) : "r"(addr));
}
__device__ __forceinline__ void mma_f16(float* c, const uint32_t* a,
                                        uint32_t b0, uint32_t b1) {
    asm volatile(
        "mma.sync.aligned.m16n8k16.row.col.f32.f16.f16.f32 "
        "{%0,%1,%2,%3}, {%4,%5,%6,%7}, {%8,%9}, {%0,%1,%2,%3};"
        : "+f"(c[0]), "+f"(c[1]), "+f"(c[2]), "+f"(c[3])
        : "r"(a[0]), "r"(a[1]), "r"(a[2]), "r"(a[3]), "r"(b0), "r"(b1));
}
__device__ __forceinline__ float ex2(float x) {
    float y;
    asm("ex2.approx.ftz.f32 %0, %1;" : "=f"(y) : "f"(x));
    return y;
}
// fp32 pair -> fp16 hi + fp16 residual
__device__ __forceinline__ void split_pack_h(float x, float y, uint32_t& hi, uint32_t& lo) {
    __half hx = __float2half_rn(x);
    __half hy = __float2half_rn(y);
    __half lx = __float2half_rn(x - __half2float(hx));
    __half ly = __float2half_rn(y - __half2float(hy));
    __half2 h(hx, hy), l(lx, ly);
    hi = *(uint32_t*)&h;
    lo = *(uint32_t*)&l;
}
__device__ __forceinline__ uint32_t pack_h2(float x, float y) {
    __half2 h(__float2half_rn(x), __float2half_rn(y));
    return *(uint32_t*)&h;
}

// ---------------------------------------------------------------------------
// Conversion kernels
// ---------------------------------------------------------------------------
__global__ __launch_bounds__(256) void cvt_split_h_kernel(
    const float4* __restrict__ in, __half* __restrict__ hi,
    __half* __restrict__ lo, int n4)
{
    int i = blockIdx.x * 256 + threadIdx.x;
    if (i >= n4) return;
    float4 v = in[i];
    float f[4] = {v.x, v.y, v.z, v.w};
    #pragma unroll
    for (int p = 0; p < 2; p++) {
        uint32_t h, l;
        split_pack_h(f[2*p+0], f[2*p+1], h, l);
        ((uint32_t*)hi)[2*i+p] = h;
        ((uint32_t*)lo)[2*i+p] = l;
    }
}

// Batched: W[K,N] fp32 -> Wt[n][k] single fp16. blockIdx.z selects weight.
__global__ __launch_bounds__(256) void cvt_wt_kernel(
    const float* __restrict__ W0, const float* __restrict__ W1,
    const float* __restrict__ W2, const float* __restrict__ W3,
    __half* __restrict__ outb)
{
    __shared__ float tile[32][33];
    const int z = blockIdx.z;
    const float* W = (z == 0) ? W0 : (z == 1) ? W1 : (z == 2) ? W2 : W3;
    __half* o = outb + (size_t)z * HD * HD;
    const int n0 = blockIdx.x * 32, k0 = blockIdx.y * 32;
    const int tx = threadIdx.x, ty = threadIdx.y;
    #pragma unroll
    for (int i = 0; i < 4; i++)
        tile[ty + 8*i][tx] = W[(size_t)(k0 + ty + 8*i) * HD + n0 + tx];
    __syncthreads();
    #pragma unroll
    for (int i = 0; i < 4; i++) {
        float v = tile[tx][ty + 8*i];
        o[(size_t)(n0 + ty + 8*i) * HD + k0 + tx] = __float2half_rn(v);
    }
}

// ---------------------------------------------------------------------------
// fp16 2-MMA GEMM: C = (Ah + Al) @ W16^T + bias. CTA 128x128, KC=64, 8 warps.
// MODE 0: fused QKV — Q/K/V all out as single fp16.
// MODE 1: O-proj — fp32 output + bias.
// ---------------------------------------------------------------------------
#define KC 64
#define GPITCH 144
#define GTILE (128 * GPITCH)            // 18432
#define GSTAGE (3 * GTILE)              // 55296: AH, AL, B
#define GEMM_SMEM (2 * GSTAGE)          // 110592

template<int MODE>
__global__ __launch_bounds__(256, 2) void gemm_mma_kernel(
    const __half* __restrict__ Ahi, const __half* __restrict__ Alo,
    const __half* __restrict__ Bh,
    const float* __restrict__ b0, const float* __restrict__ b1,
    const float* __restrict__ b2,
    __half* __restrict__ oQ, __half* __restrict__ oK, __half* __restrict__ oV,
    float* __restrict__ Cf)
{
    extern __shared__ __align__(128) char smem[];
    const uint32_t sbase = smem_to_u32(smem);
    const int tid  = threadIdx.x;
    const int wid  = tid >> 5;
    const int lane = tid & 31;
    const int bm = blockIdx.y * 128;
    const int bn = blockIdx.x * 128;
    const int wm = (wid >> 2) * 64;
    const int wn = (wid & 3) * 32;

    float acc[4][4][4];
    #pragma unroll
    for (int mt = 0; mt < 4; mt++)
        #pragma unroll
        for (int nt = 0; nt < 4; nt++)
            #pragma unroll
            for (int i = 0; i < 4; i++) acc[mt][nt][i] = 0.f;

    #define G_LOAD(SB, K0) do {                                                  \
        _Pragma("unroll")                                                        \
        for (int _i = 0; _i < 4; _i++) {                                         \
            int _lin = _i * 256 + tid;                                           \
            int _r = _lin >> 3, _c = _lin & 7;                                   \
            uint32_t _off = (uint32_t)_r * GPITCH + _c * 16;                     \
            size_t _ga = (size_t)(bm + _r) * HD + (K0) + _c * 8;                 \
            size_t _gb = (size_t)(bn + _r) * HD + (K0) + _c * 8;                 \
            cp_async16((SB) + 0*GTILE + _off, Ahi + _ga);                        \
            cp_async16((SB) + 1*GTILE + _off, Alo + _ga);                        \
            cp_async16((SB) + 2*GTILE + _off, Bh  + _gb);                        \
        }                                                                        \
        CP_COMMIT();                                                             \
    } while (0)

    G_LOAD(sbase, 0);

    const int r8 = lane & 7;
    const int g  = lane >> 3;
    const uint32_t a_row_add = (uint32_t)(r8 + ((g & 1) ? 8 : 0)) * GPITCH + ((g & 2) ? 16 : 0);
    const uint32_t b_row_add = (uint32_t)(r8 + ((g >= 2) ? 8 : 0)) * GPITCH + ((g & 1) ? 16 : 0);

    for (int t = 0; t < HD / KC; t++) {
        if (t + 1 < HD / KC) {
            G_LOAD(sbase + ((t + 1) & 1) * GSTAGE, (t + 1) * KC);
            CP_WAIT(1);
        } else {
            CP_WAIT(0);
        }
        __syncthreads();

        const uint32_t sb = sbase + (t & 1) * GSTAGE;
        #pragma unroll
        for (int ks = 0; ks < 4; ks++) {
            uint32_t bh[2][4];
            #pragma unroll
            for (int p = 0; p < 2; p++) {
                uint32_t addr = sb + 2*GTILE + (uint32_t)(wn + p * 16) * GPITCH + ks * 32 + b_row_add;
                ldsm_x4(bh[p][0], bh[p][1], bh[p][2], bh[p][3], addr);
            }
            #pragma unroll
            for (int mt = 0; mt < 4; mt++) {
                uint32_t ah[4], al[4];
                uint32_t addr = sb + (uint32_t)(wm + mt * 16) * GPITCH + ks * 32 + a_row_add;
                ldsm_x4(ah[0], ah[1], ah[2], ah[3], addr + 0*GTILE);
                ldsm_x4(al[0], al[1], al[2], al[3], addr + 1*GTILE);
                #pragma unroll
                for (int nt = 0; nt < 4; nt++) {
                    uint32_t bb0 = bh[nt >> 1][(nt & 1) * 2 + 0];
                    uint32_t bb1 = bh[nt >> 1][(nt & 1) * 2 + 1];
                    mma_f16(acc[mt][nt], ah, bb0, bb1);
                    mma_f16(acc[mt][nt], al, bb0, bb1);
                }
            }
        }
        __syncthreads();
    }

    const int er = lane >> 2;
    const int ec = (lane & 3) * 2;

    if (MODE == 0) {
        const int w  = bn >> 11;            // 0=Q,1=K,2=V
        const int ln = (bn & 2047) + wn;
        const float* bias = (w == 0) ? b0 : (w == 1) ? b1 : b2;
        __half* dst = (w == 0) ? oQ : (w == 1) ? oK : oV;
        #pragma unroll
        for (int mt = 0; mt < 4; mt++) {
            #pragma unroll
            for (int nt = 0; nt < 4; nt++) {
                int row = bm + wm + mt * 16 + er;
                int col = ln + nt * 8 + ec;
                float bb0 = bias[col], bb1 = bias[col + 1];
                *(uint32_t*)&dst[(size_t)row * HD + col] =
                    pack_h2(acc[mt][nt][0] + bb0, acc[mt][nt][1] + bb1);
                *(uint32_t*)&dst[(size_t)(row + 8) * HD + col] =
                    pack_h2(acc[mt][nt][2] + bb0, acc[mt][nt][3] + bb1);
            }
        }
    } else {
        #pragma unroll
        for (int mt = 0; mt < 4; mt++) {
            #pragma unroll
            for (int nt = 0; nt < 4; nt++) {
                int row = bm + wm + mt * 16 + er;
                int col = bn + wn + nt * 8 + ec;
                float bb0 = b0[col], bb1 = b0[col + 1];
                *(float2*)&Cf[(size_t)row * HD + col] =
                    make_float2(acc[mt][nt][0] + bb0, acc[mt][nt][1] + bb1);
                *(float2*)&Cf[(size_t)(row + 8) * HD + col] =
                    make_float2(acc[mt][nt][2] + bb0, acc[mt][nt][3] + bb1);
            }
        }
    }
}

// ---------------------------------------------------------------------------
// Tensor-core flash attention, single-fp16 1-MMA on both phases:
// S = Q16·K16 ; O += P16·V16. 4 warps, 2 CTAs/SM, K/V double-buffered.
// Output A kept as fp16 hi/lo split (protects the O-projection accuracy).
// ---------------------------------------------------------------------------
#define AVP 272
#define KTB32 (32 * AVP)            // 8704 per tile (32 rows x 128 fp16)
#define STB32 (2 * KTB32)           // 17408 per stage (K16, V16)
#define ATTN_SMEM (2 * STB32)       // 34816
#define QSTG 0                      // Q staging overlays the K/V stages

__global__ __launch_bounds__(128, 2) void attn_mma_kernel(
    const __half* __restrict__ Q16,
    const __half* __restrict__ K16, const __half* __restrict__ V16,
    const int* __restrict__ mask,
    __half* __restrict__ Ahi, __half* __restrict__ Alo)
{
    extern __shared__ __align__(128) char smem[];
    const uint32_t sbase = smem_to_u32(smem);
    const int tid  = threadIdx.x;
    const int wid  = tid >> 5;
    const int lane = tid & 31;
    const int q0 = blockIdx.x * 64;
    const int h  = blockIdx.y;
    const int b  = blockIdx.z;
    const int hc = h * DH;

    const int r8 = lane & 7;
    const int g  = lane >> 3;
    const uint32_t a_add = (uint32_t)(r8 + ((g & 1) ? 8 : 0)) * AVP + ((g & 2) ? 16 : 0);
    const uint32_t b_add = (uint32_t)(r8 + ((g >= 2) ? 8 : 0)) * AVP + ((g & 1) ? 16 : 0);
    const uint32_t v_add = (uint32_t)(r8 + ((g & 1) ? 8 : 0)) * AVP + ((g >> 1) ? 16 : 0);

    // ---- stage Q (64 x 128 fp16) and pull into registers ----
    {
        #pragma unroll
        for (int i = 0; i < 8; i++) {
            int lin = i * 128 + tid;       // 1024 16B-chunks
            int r = lin >> 4, c = lin & 15;
            size_t gq = (size_t)(b * SQ + q0 + r) * HD + hc + c * 8;
            cp_async16(sbase + QSTG + (uint32_t)r * AVP + c * 16, Q16 + gq);
        }
        CP_COMMIT();
        CP_WAIT(0);
        __syncthreads();
    }

    uint32_t qh[8][4];
    #pragma unroll
    for (int ks = 0; ks < 8; ks++) {
        uint32_t addr = (uint32_t)(16 * wid) * AVP + ks * 32 + a_add;
        ldsm_x4(qh[ks][0], qh[ks][1], qh[ks][2], qh[ks][3], sbase + QSTG + addr);
    }
    __syncthreads();   // Q staging space becomes K/V stages

    #define LOAD_CHUNK32(T, STAGE) do {                                          \
        const uint32_t _sb = sbase + (STAGE) * STB32;                            \
        _Pragma("unroll")                                                        \
        for (int _i = 0; _i < 4; _i++) {                                         \
            int _lin = _i * 128 + tid;        /* 512 16B-chunks per tensor */    \
            int _r = _lin >> 4, _c = _lin & 15;                                  \
            size_t _gk = (size_t)(b * SQ + (T) * 32 + _r) * HD + hc + _c * 8;    \
            uint32_t _off = (uint32_t)_r * AVP + _c * 16;                        \
            cp_async16(_sb + 0*KTB32 + _off, K16 + _gk);                         \
            cp_async16(_sb + 1*KTB32 + _off, V16 + _gk);                         \
        }                                                                        \
        CP_COMMIT();                                                             \
    } while (0)

    LOAD_CHUNK32(0, 0);

    float m0 = -1e30f, m1 = -1e30f, l0 = 0.f, l1 = 0.f;
    float o[16][4];
    #pragma unroll
    for (int nt = 0; nt < 16; nt++)
        #pragma unroll
        for (int i = 0; i < 4; i++) o[nt][i] = 0.f;

    const float scale2 = 0.08838834764831845f * 1.4426950408889634f;
    const int row0 = q0 + 16 * wid + (lane >> 2);
    const int c2 = (lane & 3) * 2;
    const int* mrow0 = mask + ((size_t)b * SQ + row0) * SQ;
    const int* mrow1 = mrow0 + 8 * SQ;

    for (int t = 0; t < SQ / 32; t++) {
        if (t + 1 < SQ / 32) { LOAD_CHUNK32(t + 1, (t + 1) & 1); CP_WAIT(1); }
        else CP_WAIT(0);
        __syncthreads();

        const uint32_t sb = sbase + (t & 1) * STB32;

        // ---- S = Q16 K16^T over 32 keys (1 MMA per step) ----
        float s[4][4];
        #pragma unroll
        for (int j = 0; j < 4; j++)
            #pragma unroll
            for (int i = 0; i < 4; i++) s[j][i] = 0.f;

        #pragma unroll
        for (int ks = 0; ks < 8; ks++) {
            #pragma unroll
            for (int p = 0; p < 2; p++) {
                uint32_t kh[4];
                uint32_t addr = sb + (uint32_t)(16 * p) * AVP + ks * 32 + b_add;
                ldsm_x4(kh[0], kh[1], kh[2], kh[3], addr);
                mma_f16(s[2*p],   qh[ks], kh[0], kh[1]);
                mma_f16(s[2*p+1], qh[ks], kh[2], kh[3]);
            }
        }

        // ---- mask + scale + online softmax (base-2, warp-private) ----
        const int k0 = t * 32;
        float mx0 = -1e30f, mx1 = -1e30f;
        #pragma unroll
        for (int j = 0; j < 4; j++) {
            int2 mm0 = *(const int2*)&mrow0[k0 + 8*j + c2];
            int2 mm1 = *(const int2*)&mrow1[k0 + 8*j + c2];
            s[j][0] = mm0.x ? s[j][0] * scale2 : -1e30f;
            s[j][1] = mm0.y ? s[j][1] * scale2 : -1e30f;
            s[j][2] = mm1.x ? s[j][2] * scale2 : -1e30f;
            s[j][3] = mm1.y ? s[j][3] * scale2 : -1e30f;
            mx0 = fmaxf(mx0, fmaxf(s[j][0], s[j][1]));
            mx1 = fmaxf(mx1, fmaxf(s[j][2], s[j][3]));
        }
        mx0 = fmaxf(mx0, __shfl_xor_sync(0xffffffffu, mx0, 1));
        mx0 = fmaxf(mx0, __shfl_xor_sync(0xffffffffu, mx0, 2));
        mx1 = fmaxf(mx1, __shfl_xor_sync(0xffffffffu, mx1, 1));
        mx1 = fmaxf(mx1, __shfl_xor_sync(0xffffffffu, mx1, 2));

        float mn0 = fmaxf(m0, mx0), mn1 = fmaxf(m1, mx1);
        float corr0 = ex2(m0 - mn0), corr1 = ex2(m1 - mn1);
        bool upd = (mn0 != m0) || (mn1 != m1);
        m0 = mn0; m1 = mn1;

        float ps0 = 0.f, ps1 = 0.f;
        #pragma unroll
        for (int j = 0; j < 4; j++) {
            s[j][0] = ex2(s[j][0] - m0);
            s[j][1] = ex2(s[j][1] - m0);
            s[j][2] = ex2(s[j][2] - m1);
            s[j][3] = ex2(s[j][3] - m1);
            ps0 += s[j][0] + s[j][1];
            ps1 += s[j][2] + s[j][3];
        }
        ps0 += __shfl_xor_sync(0xffffffffu, ps0, 1);
        ps0 += __shfl_xor_sync(0xffffffffu, ps0, 2);
        ps1 += __shfl_xor_sync(0xffffffffu, ps1, 1);
        ps1 += __shfl_xor_sync(0xffffffffu, ps1, 2);
        l0 = l0 * corr0 + ps0;
        l1 = l1 * corr1 + ps1;

        if (__any_sync(0xffffffffu, upd)) {
            #pragma unroll
            for (int nt = 0; nt < 16; nt++) {
                o[nt][0] *= corr0; o[nt][1] *= corr0;
                o[nt][2] *= corr1; o[nt][3] *= corr1;
            }
        }

        // ---- O += P16 V16 (1 MMA per step) ----
        #pragma unroll
        for (int ks2 = 0; ks2 < 2; ks2++) {
            uint32_t ph[4];
            ph[0] = pack_h2(s[2*ks2][0],   s[2*ks2][1]);
            ph[1] = pack_h2(s[2*ks2][2],   s[2*ks2][3]);
            ph[2] = pack_h2(s[2*ks2+1][0], s[2*ks2+1][1]);
            ph[3] = pack_h2(s[2*ks2+1][2], s[2*ks2+1][3]);
            #pragma unroll
            for (int dp = 0; dp < 8; dp++) {
                uint32_t vh[4];
                uint32_t addr = sb + 1*KTB32 + (uint32_t)(16 * ks2) * AVP + dp * 32 + v_add;
                ldsm_x4_t(vh[0], vh[1], vh[2], vh[3], addr);
                mma_f16(o[2*dp],   ph, vh[0], vh[1]);
                mma_f16(o[2*dp+1], ph, vh[2], vh[3]);
            }
        }
        __syncthreads();
    }

    // ---- epilogue: normalize, fp16 split for the O-projection ----
    const float inv0 = 1.f / l0, inv1 = 1.f / l1;
    const size_t ob0 = (size_t)(b * SQ + row0) * HD + hc;
    const size_t ob1 = ob0 + (size_t)8 * HD;
    #pragma unroll
    for (int nt = 0; nt < 16; nt++) {
        int col = 8 * nt + c2;
        uint32_t hh, ll;
        split_pack_h(o[nt][0] * inv0, o[nt][1] * inv0, hh, ll);
        *(uint32_t*)&Ahi[ob0 + col] = hh;
        *(uint32_t*)&Alo[ob0 + col] = ll;
        split_pack_h(o[nt][2] * inv1, o[nt][3] * inv1, hh, ll);
        *(uint32_t*)&Ahi[ob1 + col] = hh;
        *(uint32_t*)&Alo[ob1 + col] = ll;
    }
}

// ---------------------------------------------------------------------------

extern "C" void kernel_launch(void* const* d_in, const int* in_sizes, int n_in,
                              void* d_out, int out_size)
{
    const float* X   = (const float*)d_in[0];
    const int*   msk = (const int*)  d_in[1];
    const float* Wq  = (const float*)d_in[2];
    const float* bq  = (const float*)d_in[3];
    const float* Wk  = (const float*)d_in[4];
    const float* bk  = (const float*)d_in[5];
    const float* Wv  = (const float*)d_in[6];
    const float* bv  = (const float*)d_in[7];
    const float* Wo  = (const float*)d_in[8];
    const float* bo  = (const float*)d_in[9];
    float* out = (float*)d_out;

    __half *Q16, *K16, *V16, *Ahi, *Alo, *Xhi, *Xlo, *Wt;
    cudaGetSymbolAddress((void**)&Q16, g_Q16);
    cudaGetSymbolAddress((void**)&K16, g_K16);
    cudaGetSymbolAddress((void**)&V16, g_V16);
    cudaGetSymbolAddress((void**)&Ahi, g_Ahi);
    cudaGetSymbolAddress((void**)&Alo, g_Alo);
    cudaGetSymbolAddress((void**)&Xhi, g_Xhi);
    cudaGetSymbolAddress((void**)&Xlo, g_Xlo);
    cudaGetSymbolAddress((void**)&Wt,  g_Wt);

    const size_t WSZ = (size_t)HD * HD;
    const int n4 = MR * HD / 4;

    cudaFuncSetAttribute(gemm_mma_kernel<0>,
                         cudaFuncAttributeMaxDynamicSharedMemorySize, GEMM_SMEM);
    cudaFuncSetAttribute(gemm_mma_kernel<1>,
                         cudaFuncAttributeMaxDynamicSharedMemorySize, GEMM_SMEM);
    cudaFuncSetAttribute(attn_mma_kernel,
                         cudaFuncAttributeMaxDynamicSharedMemorySize, ATTN_SMEM);

    // 1. fp16 hi/lo split of X; batched weight transpose -> single fp16
    cvt_split_h_kernel<<<n4 / 256, 256>>>((const float4*)X, Xhi, Xlo, n4);
    dim3 wg(HD / 32, HD / 32, 4), wb(32, 8);
    cvt_wt_kernel<<<wg, wb>>>(Wq, Wk, Wv, Wo, Wt);

    // 2. Fused Q/K/V projection -> single fp16 outputs
    dim3 gq(3 * HD / 128, MR / 128);   // (48, 32)
    gemm_mma_kernel<0><<<gq, 256, GEMM_SMEM>>>(
        Xhi, Xlo, Wt, bq, bk, bv,
        Q16, K16, V16, nullptr);

    // 3. fp16 1-MMA flash attention -> fp16 split A
    dim3 ga(SQ / 64, NH, BB);          // (32, 16, 2)
    attn_mma_kernel<<<ga, 128, ATTN_SMEM>>>(Q16, K16, V16, msk, Ahi, Alo);

    // 4. output projection (fp16 2-MMA) -> fp32 out
    dim3 go(HD / 128, MR / 128);       // (16, 32)
    gemm_mma_kernel<1><<<go, 256, GEMM_SMEM>>>(
        Ahi, Alo, Wt + 3*WSZ, bo, bo, bo,
        nullptr, nullptr, nullptr, out);
}

// round 13
// speedup vs baseline: 2.3390x; 1.3917x over previous
#include <cuda_runtime.h>
#include <cuda_fp16.h>
#include <cstdint>

#define HD 2048
#define NH 16
#define DH 128
#define BB 2
#define SQ 2048
#define MR (BB*SQ)   // 4096 rows

// ---------------------------------------------------------------------------
// Scratch (device globals; no allocations allowed)
// ---------------------------------------------------------------------------
__device__ __half g_Q16[(size_t)MR*HD];
__device__ __half g_K16[(size_t)MR*HD];
__device__ __half g_V16[(size_t)MR*HD];
__device__ __half g_A16[(size_t)MR*HD];
__device__ __half g_X16[(size_t)MR*HD];
__device__ __half g_Wt[4][(size_t)HD*HD];    // transposed [n][k], fp16; Q,K,V contiguous

// ---------------------------------------------------------------------------
// PTX helpers (compute_103-safe)
// ---------------------------------------------------------------------------
__device__ __forceinline__ uint32_t smem_to_u32(const void* p) {
    uint32_t a;
    asm("{ .reg .u64 t; cvta.to.shared.u64 t, %1; cvt.u32.u64 %0, t; }"
        : "=r"(a) : "l"(p));
    return a;
}
__device__ __forceinline__ void cp_async16(uint32_t s, const void* g) {
    asm volatile("cp.async.cg.shared.global [%0], [%1], 16;" :: "r"(s), "l"(g));
}
#define CP_COMMIT() asm volatile("cp.async.commit_group;" ::: "memory")
#define CP_WAIT(n)  asm volatile("cp.async.wait_group %0;" :: "n"(n) : "memory")

__device__ __forceinline__ void ldsm_x4(uint32_t& r0, uint32_t& r1,
                                        uint32_t& r2, uint32_t& r3, uint32_t addr) {
    asm volatile("ldmatrix.sync.aligned.m8n8.x4.shared.b16 {%0,%1,%2,%3}, [%4];"
        : "=r"(r0), "=r"(r1), "=r"(r2), "=r"(r3) : "r"(addr));
}
__device__ __forceinline__ void ldsm_x4_t(uint32_t& r0, uint32_t& r1,
                                          uint32_t& r2, uint32_t& r3, uint32_t addr) {
    asm volatile("ldmatrix.sync.aligned.m8n8.x4.trans.shared.b16 {%0,%1,%2,%3}, [%4];"
        : "=r"(r0), "=r"(r1), "=r"(r2), "=r"(r3) : "r"(addr));
}
__device__ __forceinline__ void mma_f16(float* c, const uint32_t* a,
                                        uint32_t b0, uint32_t b1) {
    asm volatile(
        "mma.sync.aligned.m16n8k16.row.col.f32.f16.f16.f32 "
        "{%0,%1,%2,%3}, {%4,%5,%6,%7}, {%8,%9}, {%0,%1,%2,%3};"
        : "+f"(c[0]), "+f"(c[1]), "+f"(c[2]), "+f"(c[3])
        : "r"(a[0]), "r"(a[1]), "r"(a[2]), "r"(a[3]), "r"(b0), "r"(b1));
}
__device__ __forceinline__ float ex2(float x) {
    float y;
    asm("ex2.approx.ftz.f32 %0, %1;" : "=f"(y) : "f"(x));
    return y;
}
__device__ __forceinline__ uint32_t pack_h2(float x, float y) {
    __half2 h(__float2half_rn(x), __float2half_rn(y));
    return *(uint32_t*)&h;
}

// ---------------------------------------------------------------------------
// Conversion kernels
// ---------------------------------------------------------------------------
__global__ __launch_bounds__(256) void cvt_h_kernel(
    const float4* __restrict__ in, __half* __restrict__ out, int n4)
{
    int i = blockIdx.x * 256 + threadIdx.x;
    if (i >= n4) return;
    float4 v = in[i];
    ((uint32_t*)out)[2*i+0] = pack_h2(v.x, v.y);
    ((uint32_t*)out)[2*i+1] = pack_h2(v.z, v.w);
}

// Batched: W[K,N] fp32 -> Wt[n][k] fp16. blockIdx.z selects weight.
__global__ __launch_bounds__(256) void cvt_wt_kernel(
    const float* __restrict__ W0, const float* __restrict__ W1,
    const float* __restrict__ W2, const float* __restrict__ W3,
    __half* __restrict__ outb)
{
    __shared__ float tile[32][33];
    const int z = blockIdx.z;
    const float* W = (z == 0) ? W0 : (z == 1) ? W1 : (z == 2) ? W2 : W3;
    __half* o = outb + (size_t)z * HD * HD;
    const int n0 = blockIdx.x * 32, k0 = blockIdx.y * 32;
    const int tx = threadIdx.x, ty = threadIdx.y;
    #pragma unroll
    for (int i = 0; i < 4; i++)
        tile[ty + 8*i][tx] = W[(size_t)(k0 + ty + 8*i) * HD + n0 + tx];
    __syncthreads();
    #pragma unroll
    for (int i = 0; i < 4; i++) {
        float v = tile[tx][ty + 8*i];
        o[(size_t)(n0 + ty + 8*i) * HD + k0 + tx] = __float2half_rn(v);
    }
}

// ---------------------------------------------------------------------------
// fp16 1-MMA GEMM: C = A16 @ W16^T + bias. CTA 128x128, KC=64, 8 warps.
// 2 smem tiles/stage (A, B), double-buffered: 73.7KB -> 2 CTAs/SM.
// MODE 0: fused QKV — Q/K/V out as fp16. MODE 1: O-proj — fp32 out + bias.
// ---------------------------------------------------------------------------
#define KC 64
#define GPITCH 144
#define GTILE (128 * GPITCH)            // 18432
#define GSTAGE (2 * GTILE)              // 36864: A, B
#define GEMM_SMEM (2 * GSTAGE)          // 73728

template<int MODE>
__global__ __launch_bounds__(256, 2) void gemm_mma_kernel(
    const __half* __restrict__ A16, const __half* __restrict__ Bh,
    const float* __restrict__ b0, const float* __restrict__ b1,
    const float* __restrict__ b2,
    __half* __restrict__ oQ, __half* __restrict__ oK, __half* __restrict__ oV,
    float* __restrict__ Cf)
{
    extern __shared__ __align__(128) char smem[];
    const uint32_t sbase = smem_to_u32(smem);
    const int tid  = threadIdx.x;
    const int wid  = tid >> 5;
    const int lane = tid & 31;
    const int bm = blockIdx.y * 128;
    const int bn = blockIdx.x * 128;
    const int wm = (wid >> 2) * 64;
    const int wn = (wid & 3) * 32;

    float acc[4][4][4];
    #pragma unroll
    for (int mt = 0; mt < 4; mt++)
        #pragma unroll
        for (int nt = 0; nt < 4; nt++)
            #pragma unroll
            for (int i = 0; i < 4; i++) acc[mt][nt][i] = 0.f;

    #define G_LOAD(SB, K0) do {                                                  \
        _Pragma("unroll")                                                        \
        for (int _i = 0; _i < 4; _i++) {                                         \
            int _lin = _i * 256 + tid;                                           \
            int _r = _lin >> 3, _c = _lin & 7;                                   \
            uint32_t _off = (uint32_t)_r * GPITCH + _c * 16;                     \
            size_t _ga = (size_t)(bm + _r) * HD + (K0) + _c * 8;                 \
            size_t _gb = (size_t)(bn + _r) * HD + (K0) + _c * 8;                 \
            cp_async16((SB) + 0*GTILE + _off, A16 + _ga);                        \
            cp_async16((SB) + 1*GTILE + _off, Bh  + _gb);                        \
        }                                                                        \
        CP_COMMIT();                                                             \
    } while (0)

    G_LOAD(sbase, 0);

    const int r8 = lane & 7;
    const int g  = lane >> 3;
    const uint32_t a_row_add = (uint32_t)(r8 + ((g & 1) ? 8 : 0)) * GPITCH + ((g & 2) ? 16 : 0);
    const uint32_t b_row_add = (uint32_t)(r8 + ((g >= 2) ? 8 : 0)) * GPITCH + ((g & 1) ? 16 : 0);

    for (int t = 0; t < HD / KC; t++) {
        if (t + 1 < HD / KC) {
            G_LOAD(sbase + ((t + 1) & 1) * GSTAGE, (t + 1) * KC);
            CP_WAIT(1);
        } else {
            CP_WAIT(0);
        }
        __syncthreads();

        const uint32_t sb = sbase + (t & 1) * GSTAGE;
        #pragma unroll
        for (int ks = 0; ks < 4; ks++) {
            uint32_t bh[2][4];
            #pragma unroll
            for (int p = 0; p < 2; p++) {
                uint32_t addr = sb + 1*GTILE + (uint32_t)(wn + p * 16) * GPITCH + ks * 32 + b_row_add;
                ldsm_x4(bh[p][0], bh[p][1], bh[p][2], bh[p][3], addr);
            }
            #pragma unroll
            for (int mt = 0; mt < 4; mt++) {
                uint32_t ah[4];
                uint32_t addr = sb + (uint32_t)(wm + mt * 16) * GPITCH + ks * 32 + a_row_add;
                ldsm_x4(ah[0], ah[1], ah[2], ah[3], addr);
                #pragma unroll
                for (int nt = 0; nt < 4; nt++) {
                    uint32_t bb0 = bh[nt >> 1][(nt & 1) * 2 + 0];
                    uint32_t bb1 = bh[nt >> 1][(nt & 1) * 2 + 1];
                    mma_f16(acc[mt][nt], ah, bb0, bb1);
                }
            }
        }
        __syncthreads();
    }

    const int er = lane >> 2;
    const int ec = (lane & 3) * 2;

    if (MODE == 0) {
        const int w  = bn >> 11;            // 0=Q,1=K,2=V
        const int ln = (bn & 2047) + wn;
        const float* bias = (w == 0) ? b0 : (w == 1) ? b1 : b2;
        __half* dst = (w == 0) ? oQ : (w == 1) ? oK : oV;
        #pragma unroll
        for (int mt = 0; mt < 4; mt++) {
            #pragma unroll
            for (int nt = 0; nt < 4; nt++) {
                int row = bm + wm + mt * 16 + er;
                int col = ln + nt * 8 + ec;
                float bb0 = bias[col], bb1 = bias[col + 1];
                *(uint32_t*)&dst[(size_t)row * HD + col] =
                    pack_h2(acc[mt][nt][0] + bb0, acc[mt][nt][1] + bb1);
                *(uint32_t*)&dst[(size_t)(row + 8) * HD + col] =
                    pack_h2(acc[mt][nt][2] + bb0, acc[mt][nt][3] + bb1);
            }
        }
    } else {
        #pragma unroll
        for (int mt = 0; mt < 4; mt++) {
            #pragma unroll
            for (int nt = 0; nt < 4; nt++) {
                int row = bm + wm + mt * 16 + er;
                int col = bn + wn + nt * 8 + ec;
                float bb0 = b0[col], bb1 = b0[col + 1];
                *(float2*)&Cf[(size_t)row * HD + col] =
                    make_float2(acc[mt][nt][0] + bb0, acc[mt][nt][1] + bb1);
                *(float2*)&Cf[(size_t)(row + 8) * HD + col] =
                    make_float2(acc[mt][nt][2] + bb0, acc[mt][nt][3] + bb1);
            }
        }
    }
}

// ---------------------------------------------------------------------------
// Tensor-core flash attention, fp16 1-MMA both phases. 4 warps, 2 CTAs/SM.
// Output A as single fp16 (O-proj is 1-MMA now).
// ---------------------------------------------------------------------------
#define AVP 272
#define KTB32 (32 * AVP)            // 8704 per tile (32 rows x 128 fp16)
#define STB32 (2 * KTB32)           // 17408 per stage (K16, V16)
#define ATTN_SMEM (2 * STB32)       // 34816
#define QSTG 0                      // Q staging overlays the K/V stages

__global__ __launch_bounds__(128, 2) void attn_mma_kernel(
    const __half* __restrict__ Q16,
    const __half* __restrict__ K16, const __half* __restrict__ V16,
    const int* __restrict__ mask,
    __half* __restrict__ A16)
{
    extern __shared__ __align__(128) char smem[];
    const uint32_t sbase = smem_to_u32(smem);
    const int tid  = threadIdx.x;
    const int wid  = tid >> 5;
    const int lane = tid & 31;
    const int q0 = blockIdx.x * 64;
    const int h  = blockIdx.y;
    const int b  = blockIdx.z;
    const int hc = h * DH;

    const int r8 = lane & 7;
    const int g  = lane >> 3;
    const uint32_t a_add = (uint32_t)(r8 + ((g & 1) ? 8 : 0)) * AVP + ((g & 2) ? 16 : 0);
    const uint32_t b_add = (uint32_t)(r8 + ((g >= 2) ? 8 : 0)) * AVP + ((g & 1) ? 16 : 0);
    const uint32_t v_add = (uint32_t)(r8 + ((g & 1) ? 8 : 0)) * AVP + ((g >> 1) ? 16 : 0);

    // ---- stage Q (64 x 128 fp16) and pull into registers ----
    {
        #pragma unroll
        for (int i = 0; i < 8; i++) {
            int lin = i * 128 + tid;       // 1024 16B-chunks
            int r = lin >> 4, c = lin & 15;
            size_t gq = (size_t)(b * SQ + q0 + r) * HD + hc + c * 8;
            cp_async16(sbase + QSTG + (uint32_t)r * AVP + c * 16, Q16 + gq);
        }
        CP_COMMIT();
        CP_WAIT(0);
        __syncthreads();
    }

    uint32_t qh[8][4];
    #pragma unroll
    for (int ks = 0; ks < 8; ks++) {
        uint32_t addr = (uint32_t)(16 * wid) * AVP + ks * 32 + a_add;
        ldsm_x4(qh[ks][0], qh[ks][1], qh[ks][2], qh[ks][3], sbase + QSTG + addr);
    }
    __syncthreads();   // Q staging space becomes K/V stages

    #define LOAD_CHUNK32(T, STAGE) do {                                          \
        const uint32_t _sb = sbase + (STAGE) * STB32;                            \
        _Pragma("unroll")                                                        \
        for (int _i = 0; _i < 4; _i++) {                                         \
            int _lin = _i * 128 + tid;        /* 512 16B-chunks per tensor */    \
            int _r = _lin >> 4, _c = _lin & 15;                                  \
            size_t _gk = (size_t)(b * SQ + (T) * 32 + _r) * HD + hc + _c * 8;    \
            uint32_t _off = (uint32_t)_r * AVP + _c * 16;                        \
            cp_async16(_sb + 0*KTB32 + _off, K16 + _gk);                         \
            cp_async16(_sb + 1*KTB32 + _off, V16 + _gk);                         \
        }                                                                        \
        CP_COMMIT();                                                             \
    } while (0)

    LOAD_CHUNK32(0, 0);

    float m0 = -1e30f, m1 = -1e30f, l0 = 0.f, l1 = 0.f;
    float o[16][4];
    #pragma unroll
    for (int nt = 0; nt < 16; nt++)
        #pragma unroll
        for (int i = 0; i < 4; i++) o[nt][i] = 0.f;

    const float scale2 = 0.08838834764831845f * 1.4426950408889634f;
    const int row0 = q0 + 16 * wid + (lane >> 2);
    const int c2 = (lane & 3) * 2;
    const int* mrow0 = mask + ((size_t)b * SQ + row0) * SQ;
    const int* mrow1 = mrow0 + 8 * SQ;

    for (int t = 0; t < SQ / 32; t++) {
        if (t + 1 < SQ / 32) { LOAD_CHUNK32(t + 1, (t + 1) & 1); CP_WAIT(1); }
        else CP_WAIT(0);
        __syncthreads();

        const uint32_t sb = sbase + (t & 1) * STB32;

        // ---- S = Q16 K16^T over 32 keys ----
        float s[4][4];
        #pragma unroll
        for (int j = 0; j < 4; j++)
            #pragma unroll
            for (int i = 0; i < 4; i++) s[j][i] = 0.f;

        #pragma unroll
        for (int ks = 0; ks < 8; ks++) {
            #pragma unroll
            for (int p = 0; p < 2; p++) {
                uint32_t kh[4];
                uint32_t addr = sb + (uint32_t)(16 * p) * AVP + ks * 32 + b_add;
                ldsm_x4(kh[0], kh[1], kh[2], kh[3], addr);
                mma_f16(s[2*p],   qh[ks], kh[0], kh[1]);
                mma_f16(s[2*p+1], qh[ks], kh[2], kh[3]);
            }
        }

        // ---- mask + scale + online softmax (base-2, warp-private) ----
        const int k0 = t * 32;
        float mx0 = -1e30f, mx1 = -1e30f;
        #pragma unroll
        for (int j = 0; j < 4; j++) {
            int2 mm0 = *(const int2*)&mrow0[k0 + 8*j + c2];
            int2 mm1 = *(const int2*)&mrow1[k0 + 8*j + c2];
            s[j][0] = mm0.x ? s[j][0] * scale2 : -1e30f;
            s[j][1] = mm0.y ? s[j][1] * scale2 : -1e30f;
            s[j][2] = mm1.x ? s[j][2] * scale2 : -1e30f;
            s[j][3] = mm1.y ? s[j][3] * scale2 : -1e30f;
            mx0 = fmaxf(mx0, fmaxf(s[j][0], s[j][1]));
            mx1 = fmaxf(mx1, fmaxf(s[j][2], s[j][3]));
        }
        mx0 = fmaxf(mx0, __shfl_xor_sync(0xffffffffu, mx0, 1));
        mx0 = fmaxf(mx0, __shfl_xor_sync(0xffffffffu, mx0, 2));
        mx1 = fmaxf(mx1, __shfl_xor_sync(0xffffffffu, mx1, 1));
        mx1 = fmaxf(mx1, __shfl_xor_sync(0xffffffffu, mx1, 2));

        float mn0 = fmaxf(m0, mx0), mn1 = fmaxf(m1, mx1);
        float corr0 = ex2(m0 - mn0), corr1 = ex2(m1 - mn1);
        bool upd = (mn0 != m0) || (mn1 != m1);
        m0 = mn0; m1 = mn1;

        float ps0 = 0.f, ps1 = 0.f;
        #pragma unroll
        for (int j = 0; j < 4; j++) {
            s[j][0] = ex2(s[j][0] - m0);
            s[j][1] = ex2(s[j][1] - m0);
            s[j][2] = ex2(s[j][2] - m1);
            s[j][3] = ex2(s[j][3] - m1);
            ps0 += s[j][0] + s[j][1];
            ps1 += s[j][2] + s[j][3];
        }
        ps0 += __shfl_xor_sync(0xffffffffu, ps0, 1);
        ps0 += __shfl_xor_sync(0xffffffffu, ps0, 2);
        ps1 += __shfl_xor_sync(0xffffffffu, ps1, 1);
        ps1 += __shfl_xor_sync(0xffffffffu, ps1, 2);
        l0 = l0 * corr0 + ps0;
        l1 = l1 * corr1 + ps1;

        if (__any_sync(0xffffffffu, upd)) {
            #pragma unroll
            for (int nt = 0; nt < 16; nt++) {
                o[nt][0] *= corr0; o[nt][1] *= corr0;
                o[nt][2] *= corr1; o[nt][3] *= corr1;
            }
        }

        // ---- O += P16 V16 ----
        #pragma unroll
        for (int ks2 = 0; ks2 < 2; ks2++) {
            uint32_t ph[4];
            ph[0] = pack_h2(s[2*ks2][0],   s[2*ks2][1]);
            ph[1] = pack_h2(s[2*ks2][2],   s[2*ks2][3]);
            ph[2] = pack_h2(s[2*ks2+1][0], s[2*ks2+1][1]);
            ph[3] = pack_h2(s[2*ks2+1][2], s[2*ks2+1][3]);
            #pragma unroll
            for (int dp = 0; dp < 8; dp++) {
                uint32_t vh[4];
                uint32_t addr = sb + 1*KTB32 + (uint32_t)(16 * ks2) * AVP + dp * 32 + v_add;
                ldsm_x4_t(vh[0], vh[1], vh[2], vh[3], addr);
                mma_f16(o[2*dp],   ph, vh[0], vh[1]);
                mma_f16(o[2*dp+1], ph, vh[2], vh[3]);
            }
        }
        __syncthreads();
    }

    // ---- epilogue: normalize, single fp16 out ----
    const float inv0 = 1.f / l0, inv1 = 1.f / l1;
    const size_t ob0 = (size_t)(b * SQ + row0) * HD + hc;
    const size_t ob1 = ob0 + (size_t)8 * HD;
    #pragma unroll
    for (int nt = 0; nt < 16; nt++) {
        int col = 8 * nt + c2;
        *(uint32_t*)&A16[ob0 + col] = pack_h2(o[nt][0] * inv0, o[nt][1] * inv0);
        *(uint32_t*)&A16[ob1 + col] = pack_h2(o[nt][2] * inv1, o[nt][3] * inv1);
    }
}

// ---------------------------------------------------------------------------

extern "C" void kernel_launch(void* const* d_in, const int* in_sizes, int n_in,
                              void* d_out, int out_size)
{
    const float* X   = (const float*)d_in[0];
    const int*   msk = (const int*)  d_in[1];
    const float* Wq  = (const float*)d_in[2];
    const float* bq  = (const float*)d_in[3];
    const float* Wk  = (const float*)d_in[4];
    const float* bk  = (const float*)d_in[5];
    const float* Wv  = (const float*)d_in[6];
    const float* bv  = (const float*)d_in[7];
    const float* Wo  = (const float*)d_in[8];
    const float* bo  = (const float*)d_in[9];
    float* out = (float*)d_out;

    __half *Q16, *K16, *V16, *A16, *X16, *Wt;
    cudaGetSymbolAddress((void**)&Q16, g_Q16);
    cudaGetSymbolAddress((void**)&K16, g_K16);
    cudaGetSymbolAddress((void**)&V16, g_V16);
    cudaGetSymbolAddress((void**)&A16, g_A16);
    cudaGetSymbolAddress((void**)&X16, g_X16);
    cudaGetSymbolAddress((void**)&Wt,  g_Wt);

    const size_t WSZ = (size_t)HD * HD;
    const int n4 = MR * HD / 4;

    cudaFuncSetAttribute(gemm_mma_kernel<0>,
                         cudaFuncAttributeMaxDynamicSharedMemorySize, GEMM_SMEM);
    cudaFuncSetAttribute(gemm_mma_kernel<1>,
                         cudaFuncAttributeMaxDynamicSharedMemorySize, GEMM_SMEM);
    cudaFuncSetAttribute(attn_mma_kernel,
                         cudaFuncAttributeMaxDynamicSharedMemorySize, ATTN_SMEM);

    // 1. X -> fp16; batched weight transpose -> fp16
    cvt_h_kernel<<<n4 / 256, 256>>>((const float4*)X, X16, n4);
    dim3 wg(HD / 32, HD / 32, 4), wb(32, 8);
    cvt_wt_kernel<<<wg, wb>>>(Wq, Wk, Wv, Wo, Wt);

    // 2. Fused Q/K/V projection (1-MMA) -> fp16 outputs
    dim3 gq(3 * HD / 128, MR / 128);   // (48, 32)
    gemm_mma_kernel<0><<<gq, 256, GEMM_SMEM>>>(
        X16, Wt, bq, bk, bv, Q16, K16, V16, nullptr);

    // 3. fp16 1-MMA flash attention -> fp16 A
    dim3 ga(SQ / 64, NH, BB);          // (32, 16, 2)
    attn_mma_kernel<<<ga, 128, ATTN_SMEM>>>(Q16, K16, V16, msk, A16);

    // 4. output projection (1-MMA) -> fp32 out
    dim3 go(HD / 128, MR / 128);       // (16, 32)
    gemm_mma_kernel<1><<<go, 256, GEMM_SMEM>>>(
        A16, Wt + 3*WSZ, bo, bo, bo,
        nullptr, nullptr, nullptr, out);
}

// round 14
// speedup vs baseline: 2.5556x; 1.0926x over previous
#include <cuda_runtime.h>
#include <cuda_fp16.h>
#include <cstdint>

#define HD 2048
#define NH 16
#define DH 128
#define BB 2
#define SQ 2048
#define MR (BB*SQ)   // 4096 rows

// ---------------------------------------------------------------------------
// Scratch (device globals; no allocations allowed)
// ---------------------------------------------------------------------------
__device__ __half g_Q16[(size_t)MR*HD];
__device__ __half g_K16[(size_t)MR*HD];
__device__ __half g_V16[(size_t)MR*HD];
__device__ __half g_A16[(size_t)MR*HD];
__device__ __half g_X16[(size_t)MR*HD];
__device__ __half g_Wt[4][(size_t)HD*HD];    // transposed [n][k], fp16; Q,K,V contiguous

// ---------------------------------------------------------------------------
// PTX helpers (compute_103-safe)
// ---------------------------------------------------------------------------
__device__ __forceinline__ uint32_t smem_to_u32(const void* p) {
    uint32_t a;
    asm("{ .reg .u64 t; cvta.to.shared.u64 t, %1; cvt.u32.u64 %0, t; }"
        : "=r"(a) : "l"(p));
    return a;
}
__device__ __forceinline__ void cp_async16(uint32_t s, const void* g) {
    asm volatile("cp.async.cg.shared.global [%0], [%1], 16;" :: "r"(s), "l"(g));
}
#define CP_COMMIT() asm volatile("cp.async.commit_group;" ::: "memory")
#define CP_WAIT(n)  asm volatile("cp.async.wait_group %0;" :: "n"(n) : "memory")

__device__ __forceinline__ void ldsm_x4(uint32_t& r0, uint32_t& r1,
                                        uint32_t& r2, uint32_t& r3, uint32_t addr) {
    asm volatile("ldmatrix.sync.aligned.m8n8.x4.shared.b16 {%0,%1,%2,%3}, [%4];"
        : "=r"(r0), "=r"(r1), "=r"(r2), "=r"(r3) : "r"(addr));
}
__device__ __forceinline__ void ldsm_x4_t(uint32_t& r0, uint32_t& r1,
                                          uint32_t& r2, uint32_t& r3, uint32_t addr) {
    asm volatile("ldmatrix.sync.aligned.m8n8.x4.trans.shared.b16 {%0,%1,%2,%3}, [%4];"
        : "=r"(r0), "=r"(r1), "=r"(r2), "=r"(r3) : "r"(addr));
}
__device__ __forceinline__ void mma_f16(float* c, const uint32_t* a,
                                        uint32_t b0, uint32_t b1) {
    asm volatile(
        "mma.sync.aligned.m16n8k16.row.col.f32.f16.f16.f32 "
        "{%0,%1,%2,%3}, {%4,%5,%6,%7}, {%8,%9}, {%0,%1,%2,%3};"
        : "+f"(c[0]), "+f"(c[1]), "+f"(c[2]), "+f"(c[3])
        : "r"(a[0]), "r"(a[1]), "r"(a[2]), "r"(a[3]), "r"(b0), "r"(b1));
}
__device__ __forceinline__ float ex2(float x) {
    float y;
    asm("ex2.approx.ftz.f32 %0, %1;" : "=f"(y) : "f"(x));
    return y;
}
__device__ __forceinline__ uint32_t pack_h2(float x, float y) {
    __half2 h(__float2half_rn(x), __float2half_rn(y));
    return *(uint32_t*)&h;
}

// ---------------------------------------------------------------------------
// Conversion kernels
// ---------------------------------------------------------------------------
__global__ __launch_bounds__(256) void cvt_h_kernel(
    const float4* __restrict__ in, __half* __restrict__ out, int n4)
{
    int i = blockIdx.x * 256 + threadIdx.x;
    if (i >= n4) return;
    float4 v = in[i];
    ((uint32_t*)out)[2*i+0] = pack_h2(v.x, v.y);
    ((uint32_t*)out)[2*i+1] = pack_h2(v.z, v.w);
}

// Batched: W[K,N] fp32 -> Wt[n][k] fp16. blockIdx.z selects weight.
__global__ __launch_bounds__(256) void cvt_wt_kernel(
    const float* __restrict__ W0, const float* __restrict__ W1,
    const float* __restrict__ W2, const float* __restrict__ W3,
    __half* __restrict__ outb)
{
    __shared__ float tile[32][33];
    const int z = blockIdx.z;
    const float* W = (z == 0) ? W0 : (z == 1) ? W1 : (z == 2) ? W2 : W3;
    __half* o = outb + (size_t)z * HD * HD;
    const int n0 = blockIdx.x * 32, k0 = blockIdx.y * 32;
    const int tx = threadIdx.x, ty = threadIdx.y;
    #pragma unroll
    for (int i = 0; i < 4; i++)
        tile[ty + 8*i][tx] = W[(size_t)(k0 + ty + 8*i) * HD + n0 + tx];
    __syncthreads();
    #pragma unroll
    for (int i = 0; i < 4; i++) {
        float v = tile[tx][ty + 8*i];
        o[(size_t)(n0 + ty + 8*i) * HD + k0 + tx] = __float2half_rn(v);
    }
}

// ---------------------------------------------------------------------------
// fp16 1-MMA GEMM: C = A16 @ W16^T + bias. CTA 128x128, KC=64, 8 warps.
// (unchanged from round 13)
// ---------------------------------------------------------------------------
#define KC 64
#define GPITCH 144
#define GTILE (128 * GPITCH)            // 18432
#define GSTAGE (2 * GTILE)              // 36864: A, B
#define GEMM_SMEM (2 * GSTAGE)          // 73728

template<int MODE>
__global__ __launch_bounds__(256, 2) void gemm_mma_kernel(
    const __half* __restrict__ A16, const __half* __restrict__ Bh,
    const float* __restrict__ b0, const float* __restrict__ b1,
    const float* __restrict__ b2,
    __half* __restrict__ oQ, __half* __restrict__ oK, __half* __restrict__ oV,
    float* __restrict__ Cf)
{
    extern __shared__ __align__(128) char smem[];
    const uint32_t sbase = smem_to_u32(smem);
    const int tid  = threadIdx.x;
    const int wid  = tid >> 5;
    const int lane = tid & 31;
    const int bm = blockIdx.y * 128;
    const int bn = blockIdx.x * 128;
    const int wm = (wid >> 2) * 64;
    const int wn = (wid & 3) * 32;

    float acc[4][4][4];
    #pragma unroll
    for (int mt = 0; mt < 4; mt++)
        #pragma unroll
        for (int nt = 0; nt < 4; nt++)
            #pragma unroll
            for (int i = 0; i < 4; i++) acc[mt][nt][i] = 0.f;

    #define G_LOAD(SB, K0) do {                                                  \
        _Pragma("unroll")                                                        \
        for (int _i = 0; _i < 4; _i++) {                                         \
            int _lin = _i * 256 + tid;                                           \
            int _r = _lin >> 3, _c = _lin & 7;                                   \
            uint32_t _off = (uint32_t)_r * GPITCH + _c * 16;                     \
            size_t _ga = (size_t)(bm + _r) * HD + (K0) + _c * 8;                 \
            size_t _gb = (size_t)(bn + _r) * HD + (K0) + _c * 8;                 \
            cp_async16((SB) + 0*GTILE + _off, A16 + _ga);                        \
            cp_async16((SB) + 1*GTILE + _off, Bh  + _gb);                        \
        }                                                                        \
        CP_COMMIT();                                                             \
    } while (0)

    G_LOAD(sbase, 0);

    const int r8 = lane & 7;
    const int g  = lane >> 3;
    const uint32_t a_row_add = (uint32_t)(r8 + ((g & 1) ? 8 : 0)) * GPITCH + ((g & 2) ? 16 : 0);
    const uint32_t b_row_add = (uint32_t)(r8 + ((g >= 2) ? 8 : 0)) * GPITCH + ((g & 1) ? 16 : 0);

    for (int t = 0; t < HD / KC; t++) {
        if (t + 1 < HD / KC) {
            G_LOAD(sbase + ((t + 1) & 1) * GSTAGE, (t + 1) * KC);
            CP_WAIT(1);
        } else {
            CP_WAIT(0);
        }
        __syncthreads();

        const uint32_t sb = sbase + (t & 1) * GSTAGE;
        #pragma unroll
        for (int ks = 0; ks < 4; ks++) {
            uint32_t bh[2][4];
            #pragma unroll
            for (int p = 0; p < 2; p++) {
                uint32_t addr = sb + 1*GTILE + (uint32_t)(wn + p * 16) * GPITCH + ks * 32 + b_row_add;
                ldsm_x4(bh[p][0], bh[p][1], bh[p][2], bh[p][3], addr);
            }
            #pragma unroll
            for (int mt = 0; mt < 4; mt++) {
                uint32_t ah[4];
                uint32_t addr = sb + (uint32_t)(wm + mt * 16) * GPITCH + ks * 32 + a_row_add;
                ldsm_x4(ah[0], ah[1], ah[2], ah[3], addr);
                #pragma unroll
                for (int nt = 0; nt < 4; nt++) {
                    uint32_t bb0 = bh[nt >> 1][(nt & 1) * 2 + 0];
                    uint32_t bb1 = bh[nt >> 1][(nt & 1) * 2 + 1];
                    mma_f16(acc[mt][nt], ah, bb0, bb1);
                }
            }
        }
        __syncthreads();
    }

    const int er = lane >> 2;
    const int ec = (lane & 3) * 2;

    if (MODE == 0) {
        const int w  = bn >> 11;            // 0=Q,1=K,2=V
        const int ln = (bn & 2047) + wn;
        const float* bias = (w == 0) ? b0 : (w == 1) ? b1 : b2;
        __half* dst = (w == 0) ? oQ : (w == 1) ? oK : oV;
        #pragma unroll
        for (int mt = 0; mt < 4; mt++) {
            #pragma unroll
            for (int nt = 0; nt < 4; nt++) {
                int row = bm + wm + mt * 16 + er;
                int col = ln + nt * 8 + ec;
                float bb0 = bias[col], bb1 = bias[col + 1];
                *(uint32_t*)&dst[(size_t)row * HD + col] =
                    pack_h2(acc[mt][nt][0] + bb0, acc[mt][nt][1] + bb1);
                *(uint32_t*)&dst[(size_t)(row + 8) * HD + col] =
                    pack_h2(acc[mt][nt][2] + bb0, acc[mt][nt][3] + bb1);
            }
        }
    } else {
        #pragma unroll
        for (int mt = 0; mt < 4; mt++) {
            #pragma unroll
            for (int nt = 0; nt < 4; nt++) {
                int row = bm + wm + mt * 16 + er;
                int col = bn + wn + nt * 8 + ec;
                float bb0 = b0[col], bb1 = b0[col + 1];
                *(float2*)&Cf[(size_t)row * HD + col] =
                    make_float2(acc[mt][nt][0] + bb0, acc[mt][nt][1] + bb1);
                *(float2*)&Cf[(size_t)(row + 8) * HD + col] =
                    make_float2(acc[mt][nt][2] + bb0, acc[mt][nt][3] + bb1);
            }
        }
    }
}

// ---------------------------------------------------------------------------
// Tensor-core flash attention, fp16 1-MMA, 64-key chunks (halved per-chunk
// overhead). 4 warps, 2 CTAs/SM, K/V double-buffered (69.6KB).
// ---------------------------------------------------------------------------
#define AVP 272
#define KTB64 (64 * AVP)            // 17408 per tile (64 rows x 128 fp16)
#define STB64 (2 * KTB64)           // 34816 per stage (K16, V16)
#define ATTN_SMEM (2 * STB64)       // 69632
#define QSTG 0                      // Q staging overlays the K/V stages

__global__ __launch_bounds__(128, 2) void attn_mma_kernel(
    const __half* __restrict__ Q16,
    const __half* __restrict__ K16, const __half* __restrict__ V16,
    const int* __restrict__ mask,
    __half* __restrict__ A16)
{
    extern __shared__ __align__(128) char smem[];
    const uint32_t sbase = smem_to_u32(smem);
    const int tid  = threadIdx.x;
    const int wid  = tid >> 5;
    const int lane = tid & 31;
    const int q0 = blockIdx.x * 64;
    const int h  = blockIdx.y;
    const int b  = blockIdx.z;
    const int hc = h * DH;

    const int r8 = lane & 7;
    const int g  = lane >> 3;
    const uint32_t a_add = (uint32_t)(r8 + ((g & 1) ? 8 : 0)) * AVP + ((g & 2) ? 16 : 0);
    const uint32_t b_add = (uint32_t)(r8 + ((g >= 2) ? 8 : 0)) * AVP + ((g & 1) ? 16 : 0);
    const uint32_t v_add = (uint32_t)(r8 + ((g & 1) ? 8 : 0)) * AVP + ((g >> 1) ? 16 : 0);

    // ---- stage Q (64 x 128 fp16) and pull into registers ----
    {
        #pragma unroll
        for (int i = 0; i < 8; i++) {
            int lin = i * 128 + tid;       // 1024 16B-chunks
            int r = lin >> 4, c = lin & 15;
            size_t gq = (size_t)(b * SQ + q0 + r) * HD + hc + c * 8;
            cp_async16(sbase + QSTG + (uint32_t)r * AVP + c * 16, Q16 + gq);
        }
        CP_COMMIT();
        CP_WAIT(0);
        __syncthreads();
    }

    uint32_t qh[8][4];
    #pragma unroll
    for (int ks = 0; ks < 8; ks++) {
        uint32_t addr = (uint32_t)(16 * wid) * AVP + ks * 32 + a_add;
        ldsm_x4(qh[ks][0], qh[ks][1], qh[ks][2], qh[ks][3], sbase + QSTG + addr);
    }
    __syncthreads();   // Q staging space becomes K/V stages

    #define LOAD_CHUNK64(T, STAGE) do {                                          \
        const uint32_t _sb = sbase + (STAGE) * STB64;                            \
        _Pragma("unroll")                                                        \
        for (int _i = 0; _i < 8; _i++) {                                         \
            int _lin = _i * 128 + tid;        /* 1024 16B-chunks per tensor */   \
            int _r = _lin >> 4, _c = _lin & 15;                                  \
            size_t _gk = (size_t)(b * SQ + (T) * 64 + _r) * HD + hc + _c * 8;    \
            uint32_t _off = (uint32_t)_r * AVP + _c * 16;                        \
            cp_async16(_sb + 0*KTB64 + _off, K16 + _gk);                         \
            cp_async16(_sb + 1*KTB64 + _off, V16 + _gk);                         \
        }                                                                        \
        CP_COMMIT();                                                             \
    } while (0)

    LOAD_CHUNK64(0, 0);

    float m0 = -1e30f, m1 = -1e30f, l0 = 0.f, l1 = 0.f;
    float o[16][4];
    #pragma unroll
    for (int nt = 0; nt < 16; nt++)
        #pragma unroll
        for (int i = 0; i < 4; i++) o[nt][i] = 0.f;

    const float scale2 = 0.08838834764831845f * 1.4426950408889634f;
    const int row0 = q0 + 16 * wid + (lane >> 2);
    const int c2 = (lane & 3) * 2;
    const int* mrow0 = mask + ((size_t)b * SQ + row0) * SQ;
    const int* mrow1 = mrow0 + 8 * SQ;

    for (int t = 0; t < SQ / 64; t++) {
        if (t + 1 < SQ / 64) { LOAD_CHUNK64(t + 1, (t + 1) & 1); CP_WAIT(1); }
        else CP_WAIT(0);
        __syncthreads();

        const uint32_t sb = sbase + (t & 1) * STB64;

        // ---- S = Q16 K16^T over 64 keys ----
        float s[8][4];
        #pragma unroll
        for (int j = 0; j < 8; j++)
            #pragma unroll
            for (int i = 0; i < 4; i++) s[j][i] = 0.f;

        #pragma unroll
        for (int ks = 0; ks < 8; ks++) {
            #pragma unroll
            for (int p = 0; p < 4; p++) {
                uint32_t kh[4];
                uint32_t addr = sb + (uint32_t)(16 * p) * AVP + ks * 32 + b_add;
                ldsm_x4(kh[0], kh[1], kh[2], kh[3], addr);
                mma_f16(s[2*p],   qh[ks], kh[0], kh[1]);
                mma_f16(s[2*p+1], qh[ks], kh[2], kh[3]);
            }
        }

        // ---- mask + scale + online softmax (base-2, warp-private) ----
        const int k0 = t * 64;
        float mx0 = -1e30f, mx1 = -1e30f;
        #pragma unroll
        for (int j = 0; j < 8; j++) {
            int2 mm0 = *(const int2*)&mrow0[k0 + 8*j + c2];
            int2 mm1 = *(const int2*)&mrow1[k0 + 8*j + c2];
            s[j][0] = mm0.x ? s[j][0] * scale2 : -1e30f;
            s[j][1] = mm0.y ? s[j][1] * scale2 : -1e30f;
            s[j][2] = mm1.x ? s[j][2] * scale2 : -1e30f;
            s[j][3] = mm1.y ? s[j][3] * scale2 : -1e30f;
            mx0 = fmaxf(mx0, fmaxf(s[j][0], s[j][1]));
            mx1 = fmaxf(mx1, fmaxf(s[j][2], s[j][3]));
        }
        mx0 = fmaxf(mx0, __shfl_xor_sync(0xffffffffu, mx0, 1));
        mx0 = fmaxf(mx0, __shfl_xor_sync(0xffffffffu, mx0, 2));
        mx1 = fmaxf(mx1, __shfl_xor_sync(0xffffffffu, mx1, 1));
        mx1 = fmaxf(mx1, __shfl_xor_sync(0xffffffffu, mx1, 2));

        float mn0 = fmaxf(m0, mx0), mn1 = fmaxf(m1, mx1);
        float corr0 = ex2(m0 - mn0), corr1 = ex2(m1 - mn1);
        bool upd = (mn0 != m0) || (mn1 != m1);
        m0 = mn0; m1 = mn1;

        float ps0 = 0.f, ps1 = 0.f;
        #pragma unroll
        for (int j = 0; j < 8; j++) {
            s[j][0] = ex2(s[j][0] - m0);
            s[j][1] = ex2(s[j][1] - m0);
            s[j][2] = ex2(s[j][2] - m1);
            s[j][3] = ex2(s[j][3] - m1);
            ps0 += s[j][0] + s[j][1];
            ps1 += s[j][2] + s[j][3];
        }
        ps0 += __shfl_xor_sync(0xffffffffu, ps0, 1);
        ps0 += __shfl_xor_sync(0xffffffffu, ps0, 2);
        ps1 += __shfl_xor_sync(0xffffffffu, ps1, 1);
        ps1 += __shfl_xor_sync(0xffffffffu, ps1, 2);
        l0 = l0 * corr0 + ps0;
        l1 = l1 * corr1 + ps1;

        if (__any_sync(0xffffffffu, upd)) {
            #pragma unroll
            for (int nt = 0; nt < 16; nt++) {
                o[nt][0] *= corr0; o[nt][1] *= corr0;
                o[nt][2] *= corr1; o[nt][3] *= corr1;
            }
        }

        // ---- O += P16 V16 over 64 keys ----
        #pragma unroll
        for (int ks2 = 0; ks2 < 4; ks2++) {
            uint32_t ph[4];
            ph[0] = pack_h2(s[2*ks2][0],   s[2*ks2][1]);
            ph[1] = pack_h2(s[2*ks2][2],   s[2*ks2][3]);
            ph[2] = pack_h2(s[2*ks2+1][0], s[2*ks2+1][1]);
            ph[3] = pack_h2(s[2*ks2+1][2], s[2*ks2+1][3]);
            #pragma unroll
            for (int dp = 0; dp < 8; dp++) {
                uint32_t vh[4];
                uint32_t addr = sb + 1*KTB64 + (uint32_t)(16 * ks2) * AVP + dp * 32 + v_add;
                ldsm_x4_t(vh[0], vh[1], vh[2], vh[3], addr);
                mma_f16(o[2*dp],   ph, vh[0], vh[1]);
                mma_f16(o[2*dp+1], ph, vh[2], vh[3]);
            }
        }
        __syncthreads();
    }

    // ---- epilogue: normalize, single fp16 out ----
    const float inv0 = 1.f / l0, inv1 = 1.f / l1;
    const size_t ob0 = (size_t)(b * SQ + row0) * HD + hc;
    const size_t ob1 = ob0 + (size_t)8 * HD;
    #pragma unroll
    for (int nt = 0; nt < 16; nt++) {
        int col = 8 * nt + c2;
        *(uint32_t*)&A16[ob0 + col] = pack_h2(o[nt][0] * inv0, o[nt][1] * inv0);
        *(uint32_t*)&A16[ob1 + col] = pack_h2(o[nt][2] * inv1, o[nt][3] * inv1);
    }
}

// ---------------------------------------------------------------------------

extern "C" void kernel_launch(void* const* d_in, const int* in_sizes, int n_in,
                              void* d_out, int out_size)
{
    const float* X   = (const float*)d_in[0];
    const int*   msk = (const int*)  d_in[1];
    const float* Wq  = (const float*)d_in[2];
    const float* bq  = (const float*)d_in[3];
    const float* Wk  = (const float*)d_in[4];
    const float* bk  = (const float*)d_in[5];
    const float* Wv  = (const float*)d_in[6];
    const float* bv  = (const float*)d_in[7];
    const float* Wo  = (const float*)d_in[8];
    const float* bo  = (const float*)d_in[9];
    float* out = (float*)d_out;

    __half *Q16, *K16, *V16, *A16, *X16, *Wt;
    cudaGetSymbolAddress((void**)&Q16, g_Q16);
    cudaGetSymbolAddress((void**)&K16, g_K16);
    cudaGetSymbolAddress((void**)&V16, g_V16);
    cudaGetSymbolAddress((void**)&A16, g_A16);
    cudaGetSymbolAddress((void**)&X16, g_X16);
    cudaGetSymbolAddress((void**)&Wt,  g_Wt);

    const size_t WSZ = (size_t)HD * HD;
    const int n4 = MR * HD / 4;

    cudaFuncSetAttribute(gemm_mma_kernel<0>,
                         cudaFuncAttributeMaxDynamicSharedMemorySize, GEMM_SMEM);
    cudaFuncSetAttribute(gemm_mma_kernel<1>,
                         cudaFuncAttributeMaxDynamicSharedMemorySize, GEMM_SMEM);
    cudaFuncSetAttribute(attn_mma_kernel,
                         cudaFuncAttributeMaxDynamicSharedMemorySize, ATTN_SMEM);

    // 1. X -> fp16; batched weight transpose -> fp16
    cvt_h_kernel<<<n4 / 256, 256>>>((const float4*)X, X16, n4);
    dim3 wg(HD / 32, HD / 32, 4), wb(32, 8);
    cvt_wt_kernel<<<wg, wb>>>(Wq, Wk, Wv, Wo, Wt);

    // 2. Fused Q/K/V projection (1-MMA) -> fp16 outputs
    dim3 gq(3 * HD / 128, MR / 128);   // (48, 32)
    gemm_mma_kernel<0><<<gq, 256, GEMM_SMEM>>>(
        X16, Wt, bq, bk, bv, Q16, K16, V16, nullptr);

    // 3. fp16 1-MMA flash attention (64-key chunks) -> fp16 A
    dim3 ga(SQ / 64, NH, BB);          // (32, 16, 2)
    attn_mma_kernel<<<ga, 128, ATTN_SMEM>>>(Q16, K16, V16, msk, A16);

    // 4. output projection (1-MMA) -> fp32 out
    dim3 go(HD / 128, MR / 128);       // (16, 32)
    gemm_mma_kernel<1><<<go, 256, GEMM_SMEM>>>(
        A16, Wt + 3*WSZ, bo, bo, bo,
        nullptr, nullptr, nullptr, out);
}